// round 14
// baseline (speedup 1.0000x reference)
#include <cuda_runtime.h>

#define B_  16
#define S_  1024
#define D_  64
#define H_  4
#define DFF 256
#define L_  2
#define BS  (B_ * S_)

typedef unsigned long long u64;
typedef unsigned int u32;
typedef unsigned short u16;

// ------------------------- device scratch ------------------------------------
__device__ float g_x   [BS * D_];
__device__ u16   g_qb  [BS * D_];   // q bf16, pre-scaled
__device__ u16   g_kb  [BS * D_];   // k bf16
__device__ u16   g_vb  [BS * D_];   // v bf16
__device__ float g_keep[BS];
__device__ float g_nanf[BS];
__device__ float g_bias[BS];        // 0 or -1e30 per key
__device__ float g_part[BS / 64];
__device__ u16   g_ws   [L_ * 4 * 4 * 64 * 72];  // split ffn weights, frag layout
__device__ u16   g_wqkvo[L_ * 8 * 64 * 72];      // split q,k,v,o weights (hi/lo each)
__device__ u16   g_wcls [4 * 4608];              // split cls w1/w2 (hi/lo each)
__device__ u16   g_xh  [BS * 72];                // x bf16-hi frag layout
__device__ u16   g_xl  [BS * 72];
__device__ u16   g_cxh [BS * 72];                // ctx split frag layout
__device__ u16   g_cxl [BS * 72];

// ------------------------- helpers --------------------------------------------
__device__ __forceinline__ float ex2f(float x) {
    float r; asm("ex2.approx.f32 %0, %1;" : "=f"(r) : "f"(x)); return r;
}
__device__ __forceinline__ u32 bf2(float lo, float hi) {
    u32 r; asm("cvt.rn.bf16x2.f32 %0, %1, %2;" : "=r"(r) : "f"(hi), "f"(lo)); return r;
}
__device__ __forceinline__ u16 bf1(float f) {
    u16 h; asm("cvt.rn.bf16.f32 %0, %1;" : "=h"(h) : "f"(f)); return h;
}
__device__ __forceinline__ float bf16f(u16 h) { return __uint_as_float((u32)h << 16); }
__device__ __forceinline__ float lopart(u32 h) { return __uint_as_float(h << 16); }
__device__ __forceinline__ float hipart(u32 h) { return __uint_as_float(h & 0xffff0000u); }
__device__ __forceinline__ void mma_bf16(
    float& c0, float& c1, float& c2, float& c3,
    u32 a0, u32 a1, u32 a2, u32 a3, u32 b0, u32 b1) {
    asm volatile(
        "mma.sync.aligned.m16n8k16.row.col.f32.bf16.bf16.f32 "
        "{%0,%1,%2,%3},{%4,%5,%6,%7},{%8,%9},{%0,%1,%2,%3};"
        : "+f"(c0), "+f"(c1), "+f"(c2), "+f"(c3)
        : "r"(a0), "r"(a1), "r"(a2), "r"(a3), "r"(b0), "r"(b1));
}
// permuted k-position inside a 16-group
__device__ __forceinline__ int permpos(int j) {   // j in 0..15
    int p = j >> 1, l = j & 1;
    return (p & 3) * 4 + ((p >> 2) << 1) + l;
}
// pos of an even column pair (c,c+1) in the 72-wide frag row
__device__ __forceinline__ int pairpos(int c) {
    int p = (c & 15) >> 1;
    return (c >> 4) * 16 + (p & 3) * 4 + ((p >> 2) << 1);
}
// split a float pair into hi/lo bf16x2
__device__ __forceinline__ void split2(float a, float b, u32& h, u32& l) {
    h = bf2(a, b);
    l = bf2(a - lopart(h), b - hipart(h));
}

// ------------------------- prep: nan flags + keep + bias ----------------------
__global__ void prep_kernel(const float* __restrict__ in,
                            float* __restrict__ keepv, float* __restrict__ nanf,
                            float* __restrict__ gbias) {
    int b = blockIdx.x;
    int s = threadIdx.x;            // 1024 threads
    float v = in[b * S_ + s];
    bool nan = (v != v);
    unsigned bal = __ballot_sync(0xffffffffu, nan);
    __shared__ int warp_all[32];
    __shared__ int allnan_s;
    if ((s & 31) == 0) warp_all[s >> 5] = (bal == 0xffffffffu);
    __syncthreads();
    if (s == 0) {
        int a = 1;
        #pragma unroll
        for (int i = 0; i < 32; ++i) a &= warp_all[i];
        allnan_s = a;
    }
    __syncthreads();
    float kp = (nan || allnan_s) ? 0.f : 1.f;
    keepv[b * S_ + s] = kp;
    nanf [b * S_ + s] = nan ? 1.f : 0.f;
    gbias[b * S_ + s] = nan ? -1e30f : 0.f;
}

// ------------------------- build x (fp32 + split frag emit) -------------------
__global__ void build_x_kernel(const float* __restrict__ in,
                               const float* __restrict__ emb,
                               const float* __restrict__ keepv,
                               float* __restrict__ x,
                               u16* __restrict__ xh, u16* __restrict__ xl) {
    int idx = blockIdx.x * 256 + threadIdx.x;   // BS*32
    int cp  = idx & 31;
    int row = idx >> 5;
    int s   = row & (S_ - 1);
    int c   = cp * 2;
    float kp = keepv[row];
    const float SQF = 7.93725393319377f * 8.0f;  // sqrt(63)*sqrt(64)
    float v0 = emb[s * 63 + c] * SQF * kp;
    float v1;
    if (c + 1 == 63) {
        float t = in[row];
        v1 = ((t != t) ? 0.f : t) * kp;
    } else {
        v1 = emb[s * 63 + c + 1] * SQF * kp;
    }
    x[row * 64 + c] = v0;
    x[row * 64 + c + 1] = v1;
    int pos = pairpos(c);
    u32 h, l; split2(v0, v1, h, l);
    *(u32*)&xh[(size_t)row * 72 + pos] = h;
    *(u32*)&xl[(size_t)row * 72 + pos] = l;
}

// ------------------------- unified weight prep (1 elem/thread) ----------------
// blocks [0,128): qkvo;  [128,384): ffn;  [384,416): cls w1/w2
__global__ void wprep_all_kernel(
    const float* __restrict__ wq, const float* __restrict__ wk,
    const float* __restrict__ wv, const float* __restrict__ wo,
    const float* __restrict__ w1, const float* __restrict__ w2,
    const float* __restrict__ cw1, const float* __restrict__ cw2,
    u16* __restrict__ dstqkvo, u16* __restrict__ ws, u16* __restrict__ wcls) {
    if (blockIdx.x < 128) {
        int idx = blockIdx.x * 256 + threadIdx.x;   // [0, L*4*4096)
        int region = idx >> 12;
        int i      = idx & 4095;
        int l = region >> 2, wsel = region & 3;
        const float* src = (wsel == 0 ? wq : wsel == 1 ? wk : wsel == 2 ? wv : wo) + (size_t)l * 4096;
        u16* dst = dstqkvo + ((size_t)l * 8 + wsel * 2) * 4608;
        int k = i >> 6, n = i & 63;
        int pos = (k >> 4) * 16 + permpos(k & 15);
        float val = src[k * 64 + n];
        u16 h = bf1(val);
        dst[n * 72 + pos]        = h;
        dst[4608 + n * 72 + pos] = bf1(val - bf16f(h));
    } else if (blockIdx.x < 384) {
        int idx = (blockIdx.x - 128) * 256 + threadIdx.x;   // [0, L*4*2*4096)
        int region = idx >> 13;
        int rem    = idx & 8191;
        int which  = rem >> 12;
        int i      = rem & 4095;
        int l = region >> 2, nt = region & 3;
        u16* dst = ws + (size_t)region * (4 * 64 * 72);
        int k = i >> 6, n = i & 63;
        int pos = (k >> 4) * 16 + permpos(k & 15);
        if (which == 0) {
            float wa = w1[(size_t)l * 64 * 256 + k * 256 + nt * 64 + n];
            u16 h = bf1(wa);
            dst[0 * 64 * 72 + n * 72 + pos] = h;
            dst[1 * 64 * 72 + n * 72 + pos] = bf1(wa - bf16f(h));
        } else {
            float wb = w2[(size_t)l * 256 * 64 + (nt * 64 + k) * 64 + n];
            u16 h2 = bf1(wb);
            dst[2 * 64 * 72 + n * 72 + pos] = h2;
            dst[3 * 64 * 72 + n * 72 + pos] = bf1(wb - bf16f(h2));
        }
    } else {
        int idx = (blockIdx.x - 384) * 256 + threadIdx.x;   // [0, 2*4096)
        int which = idx >> 12;
        int i = idx & 4095;
        int k = i >> 6, n = i & 63;
        int pos = (k >> 4) * 16 + permpos(k & 15);
        const float* src = which ? cw2 : cw1;
        u16* dst = wcls + which * 2 * 4608;
        float val = src[k * 64 + n];
        u16 h = bf1(val);
        dst[n * 72 + pos]        = h;
        dst[4608 + n * 72 + pos] = bf1(val - bf16f(h));
    }
}

// ------------------------- tensor-core QKV (hi-only, n-split) -----------------
// grid (BS/64, 3, 2): z = column half. Each block: 4.6 KB weights, 16 mma/warp.
__global__ void __launch_bounds__(128) qkv_mma_kernel(
    const u16* __restrict__ xh,
    const u16* __restrict__ wsplit,   // [3][2][4608] region for this layer
    const float* __restrict__ bq, const float* __restrict__ bk, const float* __restrict__ bv_,
    u16* __restrict__ qb, u16* __restrict__ kb, u16* __restrict__ vb) {
    __shared__ __align__(16) u16 swq[32 * 72];   // 4608 B (32 output cols)
    int tid = threadIdx.x, w = tid >> 5, lane = tid & 31;
    int gid = lane >> 2, tig = lane & 3;
    int m0 = blockIdx.x * 64;
    int wsel = blockIdx.y;
    int nh   = blockIdx.z;           // column half: 0 -> cols 0..31, 1 -> 32..63
    int r0 = m0 + w * 16 + gid;

    {   // copy this half's hi weights (rows 32*nh .. 32*nh+31)
        const float4* src = (const float4*)(wsplit + (size_t)wsel * 2 * 4608 + nh * 32 * 72);
        float4* dst = (float4*)swq;
        for (int i = tid; i < 288; i += 128) dst[i] = src[i];
    }

    u32 Ah[4][4];
    {
        const u16* ph0 = xh + (size_t)r0 * 72;
        const u16* ph8 = xh + (size_t)(r0 + 8) * 72;
        #pragma unroll
        for (int gk = 0; gk < 4; ++gk) {
            uint2 t0 = *(const uint2*)(ph0 + gk * 16 + tig * 4);
            uint2 t1 = *(const uint2*)(ph8 + gk * 16 + tig * 4);
            Ah[gk][0] = t0.x; Ah[gk][2] = t0.y;
            Ah[gk][1] = t1.x; Ah[gk][3] = t1.y;
        }
    }
    __syncthreads();

    float C2[4][4];
    #pragma unroll
    for (int j = 0; j < 4; ++j)
        #pragma unroll
        for (int i = 0; i < 4; ++i) C2[j][i] = 0.f;

    #pragma unroll
    for (int j = 0; j < 4; ++j) {
        #pragma unroll
        for (int t = 0; t < 4; ++t) {
            uint2 bh = *(const uint2*)(swq + (8 * j + gid) * 72 + t * 16 + tig * 4);
            mma_bf16(C2[j][0], C2[j][1], C2[j][2], C2[j][3],
                     Ah[t][0], Ah[t][1], Ah[t][2], Ah[t][3], bh.x, bh.y);
        }
    }

    const float SC = 0.25f * 1.4426950408889634f;  // applied only to q
    float sc = (wsel == 0) ? SC : 1.f;
    const float* bias = wsel == 0 ? bq : wsel == 1 ? bk : bv_;
    u16* out = wsel == 0 ? qb : wsel == 1 ? kb : vb;
    #pragma unroll
    for (int j = 0; j < 4; ++j) {
        int c = nh * 32 + 8 * j + 2 * tig;
        float2 bb = *(const float2*)(bias + c);
        *(u32*)(out + (size_t)r0 * 64 + c)       = bf2((C2[j][0] + bb.x) * sc, (C2[j][1] + bb.y) * sc);
        *(u32*)(out + (size_t)(r0 + 8) * 64 + c) = bf2((C2[j][2] + bb.x) * sc, (C2[j][3] + bb.y) * sc);
    }
}

// ------------------------- tensor-core flash attention (16 q/warp) ------------
#define KCHUNK 64
__global__ void __launch_bounds__(256) attn_mma_kernel(
    const u16* __restrict__ qb, const u16* __restrict__ kb,
    const u16* __restrict__ vb, const float* __restrict__ gbias,
    const float* __restrict__ nanf,
    u16* __restrict__ cxh, u16* __restrict__ cxl) {
    __shared__ __align__(16) u16 Ks[2][KCHUNK * 18];
    __shared__ __align__(16) u16 Vt[2][16 * 66];
    __shared__ float bias[2][KCHUNK];

    int tid = threadIdx.x;
    int w   = tid >> 5;
    int lane = tid & 31;
    int gid = lane >> 2;
    int tig = lane & 3;
    int bh = blockIdx.y;
    int b = bh >> 2, h = bh & 3;
    int qbase = blockIdx.x * 128;        // 128 queries per block, 16 per warp
    size_t bS = (size_t)b * S_;

    int key = tid >> 2, d4 = tid & 3;

    u64 kv0 = *(const u64*)(kb + (bS + key) * 64 + h * 16 + d4 * 4);
    u64 vv0 = *(const u64*)(vb + (bS + key) * 64 + h * 16 + d4 * 4);
    float bb0 = (tid < KCHUNK) ? gbias[bS + tid] : 0.f;

    // Q fragments direct from global (pre-scaled bf16)
    u32 qa[4];
    {
        size_t row = bS + qbase + w * 16 + gid;
        qa[0] = *(const u32*)(qb + row * 64 + h * 16 + 2 * tig);
        qa[1] = *(const u32*)(qb + (row + 8) * 64 + h * 16 + 2 * tig);
        qa[2] = *(const u32*)(qb + row * 64 + h * 16 + 8 + 2 * tig);
        qa[3] = *(const u32*)(qb + (row + 8) * 64 + h * 16 + 8 + 2 * tig);
    }

    {
        *(u32*)((char*)Ks[0] + key * 36 + d4 * 8)     = (u32)kv0;
        *(u32*)((char*)Ks[0] + key * 36 + d4 * 8 + 4) = (u32)(kv0 >> 32);
        Vt[0][(d4 * 4 + 0) * 66 + key] = (u16)vv0;
        Vt[0][(d4 * 4 + 1) * 66 + key] = (u16)(vv0 >> 16);
        Vt[0][(d4 * 4 + 2) * 66 + key] = (u16)(vv0 >> 32);
        Vt[0][(d4 * 4 + 3) * 66 + key] = (u16)(vv0 >> 48);
        if (tid < KCHUNK) bias[0][tid] = bb0;
    }
    __syncthreads();

    float z0 = 0.f, z1 = 0.f;
    float cd[2][4];
    #pragma unroll
    for (int dt = 0; dt < 2; ++dt)
        #pragma unroll
        for (int i = 0; i < 4; ++i) cd[dt][i] = 0.f;

    for (int ch = 0; ch < S_ / KCHUNK; ++ch) {
        int cur = ch & 1;
        u64 kvn = 0, vvn = 0; float bbn = 0.f;
        if (ch + 1 < S_ / KCHUNK) {
            size_t nb = bS + (ch + 1) * KCHUNK;
            kvn = *(const u64*)(kb + (nb + key) * 64 + h * 16 + d4 * 4);
            vvn = *(const u64*)(vb + (nb + key) * 64 + h * 16 + d4 * 4);
            if (tid < KCHUNK) bbn = gbias[nb + tid];
        }

        const u16* KsC = Ks[cur];
        const u16* VtC = Vt[cur];
        const float* biC = bias[cur];

        #pragma unroll
        for (int kbk = 0; kbk < KCHUNK; kbk += 16) {
            u32 kb0a = *(const u32*)((char*)KsC + (kbk + gid) * 36 + tig * 4);
            u32 kb1a = *(const u32*)((char*)KsC + (kbk + gid) * 36 + tig * 4 + 16);
            u32 kb0b = *(const u32*)((char*)KsC + (kbk + 8 + gid) * 36 + tig * 4);
            u32 kb1b = *(const u32*)((char*)KsC + (kbk + 8 + gid) * 36 + tig * 4 + 16);
            u32 vb00 = *(const u32*)((char*)VtC + (gid * 66 + kbk + 2 * tig) * 2);
            u32 vb01 = *(const u32*)((char*)VtC + (gid * 66 + kbk + 8 + 2 * tig) * 2);
            u32 vb10 = *(const u32*)((char*)VtC + ((gid + 8) * 66 + kbk + 2 * tig) * 2);
            u32 vb11 = *(const u32*)((char*)VtC + ((gid + 8) * 66 + kbk + 8 + 2 * tig) * 2);
            float2 bv0 = *(const float2*)(biC + kbk + 2 * tig);
            float2 bv1 = *(const float2*)(biC + kbk + 8 + 2 * tig);

            float c0 = bv0.x, c1 = bv0.y, c2 = bv0.x, c3 = bv0.y;
            mma_bf16(c0, c1, c2, c3, qa[0], qa[1], qa[2], qa[3], kb0a, kb1a);
            float d0 = bv1.x, d1 = bv1.y, d2 = bv1.x, d3 = bv1.y;
            mma_bf16(d0, d1, d2, d3, qa[0], qa[1], qa[2], qa[3], kb0b, kb1b);

            float p0 = ex2f(c0), p1 = ex2f(c1);
            float p2 = ex2f(c2), p3 = ex2f(c3);
            float p4 = ex2f(d0), p5 = ex2f(d1);
            float p6 = ex2f(d2), p7 = ex2f(d3);
            z0 += (p0 + p1) + (p4 + p5);
            z1 += (p2 + p3) + (p6 + p7);

            u32 pa0 = bf2(p0, p1), pa1 = bf2(p2, p3);
            u32 pa2 = bf2(p4, p5), pa3 = bf2(p6, p7);
            mma_bf16(cd[0][0], cd[0][1], cd[0][2], cd[0][3],
                     pa0, pa1, pa2, pa3, vb00, vb01);
            mma_bf16(cd[1][0], cd[1][1], cd[1][2], cd[1][3],
                     pa0, pa1, pa2, pa3, vb10, vb11);
        }

        if (ch + 1 < S_ / KCHUNK) {
            int nxt = cur ^ 1;
            *(u32*)((char*)Ks[nxt] + key * 36 + d4 * 8)     = (u32)kvn;
            *(u32*)((char*)Ks[nxt] + key * 36 + d4 * 8 + 4) = (u32)(kvn >> 32);
            Vt[nxt][(d4 * 4 + 0) * 66 + key] = (u16)vvn;
            Vt[nxt][(d4 * 4 + 1) * 66 + key] = (u16)(vvn >> 16);
            Vt[nxt][(d4 * 4 + 2) * 66 + key] = (u16)(vvn >> 32);
            Vt[nxt][(d4 * 4 + 3) * 66 + key] = (u16)(vvn >> 48);
            if (tid < KCHUNK) bias[nxt][tid] = bbn;
            __syncthreads();
        }
    }

    z0 += __shfl_xor_sync(0xffffffffu, z0, 1);
    z0 += __shfl_xor_sync(0xffffffffu, z0, 2);
    z1 += __shfl_xor_sync(0xffffffffu, z1, 1);
    z1 += __shfl_xor_sync(0xffffffffu, z1, 2);

    size_t g0 = bS + qbase + w * 16 + gid;
    size_t g1 = g0 + 8;
    float rk0 = (nanf[g0] == 0.f) ? 1.f : 0.f;
    float rk1 = (nanf[g1] == 0.f) ? 1.f : 0.f;
    float rz0 = (rk0 != 0.f && z0 > 0.f) ? (1.f / z0) : 0.f;
    float rz1 = (rk1 != 0.f && z1 > 0.f) ? (1.f / z1) : 0.f;

    int posA = h * 16 + tig * 4;
    int posB = posA + 2;
    size_t row0 = g0 * 72;
    size_t row1 = g1 * 72;
    u32 hh, ll;
    split2(cd[0][0] * rz0, cd[0][1] * rz0, hh, ll);
    *(u32*)&cxh[row0 + posA] = hh; *(u32*)&cxl[row0 + posA] = ll;
    split2(cd[1][0] * rz0, cd[1][1] * rz0, hh, ll);
    *(u32*)&cxh[row0 + posB] = hh; *(u32*)&cxl[row0 + posB] = ll;
    split2(cd[0][2] * rz1, cd[0][3] * rz1, hh, ll);
    *(u32*)&cxh[row1 + posA] = hh; *(u32*)&cxl[row1 + posA] = ll;
    split2(cd[1][2] * rz1, cd[1][3] * rz1, hh, ll);
    *(u32*)&cxh[row1 + posB] = hh; *(u32*)&cxl[row1 + posB] = ll;
}

// ------------------------- fused WO + LN1 + FFN + LN2 kernel -------------------
__global__ void __launch_bounds__(128) wo_ffn_kernel(
    const u16* __restrict__ cxh, const u16* __restrict__ cxl,
    const float* __restrict__ residx, const u16* __restrict__ wo_w,
    const u16* __restrict__ ws,
    const float* __restrict__ g1, const float* __restrict__ be1,
    const float* __restrict__ g2, const float* __restrict__ be2,
    const float* __restrict__ keep, float* __restrict__ xout,
    u16* __restrict__ xh, u16* __restrict__ xl) {
    extern __shared__ u16 sw[];   // 4 * 64 * 72 u16 = 36864 B
    int tid = threadIdx.x, w = tid >> 5, lane = tid & 31;
    int gid = lane >> 2, tig = lane & 3;
    int m0 = blockIdx.x * 64;
    int r0 = m0 + w * 16 + gid;

    float C2[8][4];
    #pragma unroll
    for (int j = 0; j < 8; ++j)
        #pragma unroll
        for (int i = 0; i < 4; ++i) C2[j][i] = 0.f;
    {
        u32 Ah[4][4], Al[4][4];
        const u16* ph0 = cxh + (size_t)r0 * 72;
        const u16* ph8 = cxh + (size_t)(r0 + 8) * 72;
        const u16* pl0 = cxl + (size_t)r0 * 72;
        const u16* pl8 = cxl + (size_t)(r0 + 8) * 72;
        #pragma unroll
        for (int gk = 0; gk < 4; ++gk) {
            uint2 t0 = *(const uint2*)(ph0 + gk * 16 + tig * 4);
            uint2 t1 = *(const uint2*)(ph8 + gk * 16 + tig * 4);
            Ah[gk][0] = t0.x; Ah[gk][2] = t0.y;
            Ah[gk][1] = t1.x; Ah[gk][3] = t1.y;
            uint2 s0 = *(const uint2*)(pl0 + gk * 16 + tig * 4);
            uint2 s1 = *(const uint2*)(pl8 + gk * 16 + tig * 4);
            Al[gk][0] = s0.x; Al[gk][2] = s0.y;
            Al[gk][1] = s1.x; Al[gk][3] = s1.y;
        }
        const u16* Wh = wo_w;
        const u16* Wl = wo_w + 4608;
        #pragma unroll
        for (int j = 0; j < 8; ++j) {
            #pragma unroll
            for (int t = 0; t < 4; ++t) {
                uint2 bh = *(const uint2*)(Wh + (8 * j + gid) * 72 + t * 16 + tig * 4);
                uint2 bl = *(const uint2*)(Wl + (8 * j + gid) * 72 + t * 16 + tig * 4);
                mma_bf16(C2[j][0], C2[j][1], C2[j][2], C2[j][3], Ah[t][0], Ah[t][1], Ah[t][2], Ah[t][3], bh.x, bh.y);
                mma_bf16(C2[j][0], C2[j][1], C2[j][2], C2[j][3], Ah[t][0], Ah[t][1], Ah[t][2], Ah[t][3], bl.x, bl.y);
                mma_bf16(C2[j][0], C2[j][1], C2[j][2], C2[j][3], Al[t][0], Al[t][1], Al[t][2], Al[t][3], bh.x, bh.y);
            }
        }
    }

    float kp0 = keep[r0], kp1 = keep[r0 + 8];

    u32 A1h[4][4], A1l[4][4];
    {
        float v0[16], v1[16];
        float s0 = 0.f, q0 = 0.f, s1 = 0.f, q1 = 0.f;
        #pragma unroll
        for (int j = 0; j < 8; ++j) {
            float2 ra = *(const float2*)(residx + (size_t)r0 * 64 + 8 * j + 2 * tig);
            float2 rb = *(const float2*)(residx + (size_t)(r0 + 8) * 64 + 8 * j + 2 * tig);
            float a0v = C2[j][0] + ra.x, a1v = C2[j][1] + ra.y;
            float b0v = C2[j][2] + rb.x, b1v = C2[j][3] + rb.y;
            v0[2 * j] = a0v; v0[2 * j + 1] = a1v;
            v1[2 * j] = b0v; v1[2 * j + 1] = b1v;
            s0 += a0v + a1v; q0 += a0v * a0v + a1v * a1v;
            s1 += b0v + b1v; q1 += b0v * b0v + b1v * b1v;
        }
        s0 += __shfl_xor_sync(0xffffffffu, s0, 1); s0 += __shfl_xor_sync(0xffffffffu, s0, 2);
        q0 += __shfl_xor_sync(0xffffffffu, q0, 1); q0 += __shfl_xor_sync(0xffffffffu, q0, 2);
        s1 += __shfl_xor_sync(0xffffffffu, s1, 1); s1 += __shfl_xor_sync(0xffffffffu, s1, 2);
        q1 += __shfl_xor_sync(0xffffffffu, q1, 1); q1 += __shfl_xor_sync(0xffffffffu, q1, 2);
        float m0v = s0 * (1.f / 64.f), m1v = s1 * (1.f / 64.f);
        float i0 = rsqrtf(q0 * (1.f / 64.f) - m0v * m0v + 1e-6f);
        float i1 = rsqrtf(q1 * (1.f / 64.f) - m1v * m1v + 1e-6f);
        #pragma unroll
        for (int j = 0; j < 8; ++j) {
            int c = 8 * j + 2 * tig;
            float2 gg = *(const float2*)(g1 + c);
            float2 bb = *(const float2*)(be1 + c);
            float oax = ((v0[2 * j] - m0v) * i0 * gg.x + bb.x) * kp0;
            float oay = ((v0[2 * j + 1] - m0v) * i0 * gg.y + bb.y) * kp0;
            float obx = ((v1[2 * j] - m1v) * i1 * gg.x + bb.x) * kp1;
            float oby = ((v1[2 * j + 1] - m1v) * i1 * gg.y + bb.y) * kp1;
            int gk = j >> 1, half = (j & 1) << 1;
            split2(oax, oay, A1h[gk][half], A1l[gk][half]);
            split2(obx, oby, A1h[gk][half + 1], A1l[gk][half + 1]);
        }
    }

    #pragma unroll
    for (int j = 0; j < 8; ++j)
        #pragma unroll
        for (int i = 0; i < 4; ++i) C2[j][i] = 0.f;

    for (int nt = 0; nt < 4; ++nt) {
        __syncthreads();
        {
            const float4* src = (const float4*)(ws + (size_t)nt * 4 * 64 * 72);
            float4* dst = (float4*)sw;
            #pragma unroll
            for (int i = 0; i < 18; ++i) dst[tid + i * 128] = src[tid + i * 128];
        }
        __syncthreads();
        const u16* W1h = sw;
        const u16* W1l = sw + 64 * 72;
        const u16* W2h = sw + 2 * 64 * 72;
        const u16* W2l = sw + 3 * 64 * 72;

        u32 A2h[4][4], A2l[4][4];
        #pragma unroll
        for (int t = 0; t < 4; ++t) {
            float Ca[4] = {0.f, 0.f, 0.f, 0.f};
            float Cb[4] = {0.f, 0.f, 0.f, 0.f};
            #pragma unroll
            for (int gk = 0; gk < 4; ++gk) {
                uint2 bha = *(const uint2*)(W1h + (16 * t + gid) * 72 + gk * 16 + tig * 4);
                uint2 bla = *(const uint2*)(W1l + (16 * t + gid) * 72 + gk * 16 + tig * 4);
                mma_bf16(Ca[0], Ca[1], Ca[2], Ca[3], A1h[gk][0], A1h[gk][1], A1h[gk][2], A1h[gk][3], bha.x, bha.y);
                mma_bf16(Ca[0], Ca[1], Ca[2], Ca[3], A1h[gk][0], A1h[gk][1], A1h[gk][2], A1h[gk][3], bla.x, bla.y);
                mma_bf16(Ca[0], Ca[1], Ca[2], Ca[3], A1l[gk][0], A1l[gk][1], A1l[gk][2], A1l[gk][3], bha.x, bha.y);
                uint2 bhb = *(const uint2*)(W1h + (16 * t + 8 + gid) * 72 + gk * 16 + tig * 4);
                uint2 blb = *(const uint2*)(W1l + (16 * t + 8 + gid) * 72 + gk * 16 + tig * 4);
                mma_bf16(Cb[0], Cb[1], Cb[2], Cb[3], A1h[gk][0], A1h[gk][1], A1h[gk][2], A1h[gk][3], bhb.x, bhb.y);
                mma_bf16(Cb[0], Cb[1], Cb[2], Cb[3], A1h[gk][0], A1h[gk][1], A1h[gk][2], A1h[gk][3], blb.x, blb.y);
                mma_bf16(Cb[0], Cb[1], Cb[2], Cb[3], A1l[gk][0], A1l[gk][1], A1l[gk][2], A1l[gk][3], bhb.x, bhb.y);
            }
            #pragma unroll
            for (int i = 0; i < 4; ++i) { Ca[i] = fmaxf(Ca[i], 0.f); Cb[i] = fmaxf(Cb[i], 0.f); }
            split2(Ca[0], Ca[1], A2h[t][0], A2l[t][0]);
            split2(Ca[2], Ca[3], A2h[t][1], A2l[t][1]);
            split2(Cb[0], Cb[1], A2h[t][2], A2l[t][2]);
            split2(Cb[2], Cb[3], A2h[t][3], A2l[t][3]);
        }

        #pragma unroll
        for (int j = 0; j < 8; ++j) {
            #pragma unroll
            for (int t = 0; t < 4; ++t) {
                uint2 bh = *(const uint2*)(W2h + (8 * j + gid) * 72 + t * 16 + tig * 4);
                uint2 bl = *(const uint2*)(W2l + (8 * j + gid) * 72 + t * 16 + tig * 4);
                mma_bf16(C2[j][0], C2[j][1], C2[j][2], C2[j][3], A2h[t][0], A2h[t][1], A2h[t][2], A2h[t][3], bh.x, bh.y);
                mma_bf16(C2[j][0], C2[j][1], C2[j][2], C2[j][3], A2h[t][0], A2h[t][1], A2h[t][2], A2h[t][3], bl.x, bl.y);
                mma_bf16(C2[j][0], C2[j][1], C2[j][2], C2[j][3], A2l[t][0], A2l[t][1], A2l[t][2], A2l[t][3], bh.x, bh.y);
            }
        }
    }

    float v0[16], v1[16];
    float s0 = 0.f, q0 = 0.f, s1 = 0.f, q1 = 0.f;
    #pragma unroll
    for (int j = 0; j < 8; ++j) {
        int gk = j >> 1, half = (j & 1) << 1;
        float rax = lopart(A1h[gk][half])     + lopart(A1l[gk][half]);
        float ray = hipart(A1h[gk][half])     + hipart(A1l[gk][half]);
        float rbx = lopart(A1h[gk][half + 1]) + lopart(A1l[gk][half + 1]);
        float rby = hipart(A1h[gk][half + 1]) + hipart(A1l[gk][half + 1]);
        float a0v = C2[j][0] + rax, a1v = C2[j][1] + ray;
        float b0v = C2[j][2] + rbx, b1v = C2[j][3] + rby;
        v0[2 * j] = a0v; v0[2 * j + 1] = a1v;
        v1[2 * j] = b0v; v1[2 * j + 1] = b1v;
        s0 += a0v + a1v; q0 += a0v * a0v + a1v * a1v;
        s1 += b0v + b1v; q1 += b0v * b0v + b1v * b1v;
    }
    s0 += __shfl_xor_sync(0xffffffffu, s0, 1); s0 += __shfl_xor_sync(0xffffffffu, s0, 2);
    q0 += __shfl_xor_sync(0xffffffffu, q0, 1); q0 += __shfl_xor_sync(0xffffffffu, q0, 2);
    s1 += __shfl_xor_sync(0xffffffffu, s1, 1); s1 += __shfl_xor_sync(0xffffffffu, s1, 2);
    q1 += __shfl_xor_sync(0xffffffffu, q1, 1); q1 += __shfl_xor_sync(0xffffffffu, q1, 2);
    float m0v = s0 * (1.f / 64.f), m1v = s1 * (1.f / 64.f);
    float i0 = rsqrtf(q0 * (1.f / 64.f) - m0v * m0v + 1e-6f);
    float i1 = rsqrtf(q1 * (1.f / 64.f) - m1v * m1v + 1e-6f);
    #pragma unroll
    for (int j = 0; j < 8; ++j) {
        int c = 8 * j + 2 * tig;
        float2 gg = *(const float2*)(g2 + c);
        float2 bb = *(const float2*)(be2 + c);
        float2 oa = make_float2(((v0[2 * j] - m0v) * i0 * gg.x + bb.x) * kp0,
                                ((v0[2 * j + 1] - m0v) * i0 * gg.y + bb.y) * kp0);
        float2 ob = make_float2(((v1[2 * j] - m1v) * i1 * gg.x + bb.x) * kp1,
                                ((v1[2 * j + 1] - m1v) * i1 * gg.y + bb.y) * kp1);
        *(float2*)(xout + (size_t)r0 * 64 + c) = oa;
        *(float2*)(xout + (size_t)(r0 + 8) * 64 + c) = ob;
        int pos = pairpos(c);
        u32 hh, ll;
        split2(oa.x, oa.y, hh, ll);
        *(u32*)&xh[(size_t)r0 * 72 + pos] = hh; *(u32*)&xl[(size_t)r0 * 72 + pos] = ll;
        split2(ob.x, ob.y, hh, ll);
        *(u32*)&xh[(size_t)(r0 + 8) * 72 + pos] = hh; *(u32*)&xl[(size_t)(r0 + 8) * 72 + pos] = ll;
    }
}

// ------------------------- tensor-core classifier ------------------------------
__global__ void __launch_bounds__(128) cls_mma_kernel(
    const u16* __restrict__ xh, const u16* __restrict__ xl,
    const u16* __restrict__ wcls,   // [w1h|w1l|w2h|w2l], each 4608 u16
    const float* __restrict__ b1, const float* __restrict__ b2,
    const float* __restrict__ w3, const float* __restrict__ b3,
    float* __restrict__ part) {
    __shared__ __align__(16) u16 sw[4 * 4608];   // 36864 B
    __shared__ float red[128];
    int tid = threadIdx.x, w = tid >> 5, lane = tid & 31;
    int gid = lane >> 2, tig = lane & 3;
    int m0 = blockIdx.x * 64;
    int r0 = m0 + w * 16 + gid;

    {
        const float4* src = (const float4*)wcls;
        float4* dst = (float4*)sw;
        #pragma unroll
        for (int i = 0; i < 18; ++i) dst[tid + i * 128] = src[tid + i * 128];
    }

    u32 Ah[4][4], Al[4][4];
    {
        const u16* ph0 = xh + (size_t)r0 * 72;
        const u16* ph8 = xh + (size_t)(r0 + 8) * 72;
        const u16* pl0 = xl + (size_t)r0 * 72;
        const u16* pl8 = xl + (size_t)(r0 + 8) * 72;
        #pragma unroll
        for (int gk = 0; gk < 4; ++gk) {
            uint2 t0 = *(const uint2*)(ph0 + gk * 16 + tig * 4);
            uint2 t1 = *(const uint2*)(ph8 + gk * 16 + tig * 4);
            Ah[gk][0] = t0.x; Ah[gk][2] = t0.y;
            Ah[gk][1] = t1.x; Ah[gk][3] = t1.y;
            uint2 s0 = *(const uint2*)(pl0 + gk * 16 + tig * 4);
            uint2 s1 = *(const uint2*)(pl8 + gk * 16 + tig * 4);
            Al[gk][0] = s0.x; Al[gk][2] = s0.y;
            Al[gk][1] = s1.x; Al[gk][3] = s1.y;
        }
    }
    __syncthreads();
    const u16* W1h = sw;
    const u16* W1l = sw + 4608;
    const u16* W2h = sw + 2 * 4608;
    const u16* W2l = sw + 3 * 4608;

    u32 A2h[4][4], A2l[4][4];
    #pragma unroll
    for (int t = 0; t < 4; ++t) {
        float Ca[4] = {0.f, 0.f, 0.f, 0.f};
        float Cb[4] = {0.f, 0.f, 0.f, 0.f};
        #pragma unroll
        for (int gk = 0; gk < 4; ++gk) {
            uint2 bha = *(const uint2*)(W1h + (16 * t + gid) * 72 + gk * 16 + tig * 4);
            uint2 bla = *(const uint2*)(W1l + (16 * t + gid) * 72 + gk * 16 + tig * 4);
            mma_bf16(Ca[0], Ca[1], Ca[2], Ca[3], Ah[gk][0], Ah[gk][1], Ah[gk][2], Ah[gk][3], bha.x, bha.y);
            mma_bf16(Ca[0], Ca[1], Ca[2], Ca[3], Ah[gk][0], Ah[gk][1], Ah[gk][2], Ah[gk][3], bla.x, bla.y);
            mma_bf16(Ca[0], Ca[1], Ca[2], Ca[3], Al[gk][0], Al[gk][1], Al[gk][2], Al[gk][3], bha.x, bha.y);
            uint2 bhb = *(const uint2*)(W1h + (16 * t + 8 + gid) * 72 + gk * 16 + tig * 4);
            uint2 blb = *(const uint2*)(W1l + (16 * t + 8 + gid) * 72 + gk * 16 + tig * 4);
            mma_bf16(Cb[0], Cb[1], Cb[2], Cb[3], Ah[gk][0], Ah[gk][1], Ah[gk][2], Ah[gk][3], bhb.x, bhb.y);
            mma_bf16(Cb[0], Cb[1], Cb[2], Cb[3], Ah[gk][0], Ah[gk][1], Ah[gk][2], Ah[gk][3], blb.x, blb.y);
            mma_bf16(Cb[0], Cb[1], Cb[2], Cb[3], Al[gk][0], Al[gk][1], Al[gk][2], Al[gk][3], bhb.x, bhb.y);
        }
        float2 b1a = *(const float2*)(b1 + 16 * t + 2 * tig);
        float2 b1b = *(const float2*)(b1 + 16 * t + 8 + 2 * tig);
        Ca[0] = fmaxf(Ca[0] + b1a.x, 0.f); Ca[1] = fmaxf(Ca[1] + b1a.y, 0.f);
        Ca[2] = fmaxf(Ca[2] + b1a.x, 0.f); Ca[3] = fmaxf(Ca[3] + b1a.y, 0.f);
        Cb[0] = fmaxf(Cb[0] + b1b.x, 0.f); Cb[1] = fmaxf(Cb[1] + b1b.y, 0.f);
        Cb[2] = fmaxf(Cb[2] + b1b.x, 0.f); Cb[3] = fmaxf(Cb[3] + b1b.y, 0.f);
        split2(Ca[0], Ca[1], A2h[t][0], A2l[t][0]);
        split2(Ca[2], Ca[3], A2h[t][1], A2l[t][1]);
        split2(Cb[0], Cb[1], A2h[t][2], A2l[t][2]);
        split2(Cb[2], Cb[3], A2h[t][3], A2l[t][3]);
    }

    float partial = 0.f;
    #pragma unroll
    for (int j = 0; j < 8; ++j) {
        float C2[4] = {0.f, 0.f, 0.f, 0.f};
        #pragma unroll
        for (int t = 0; t < 4; ++t) {
            uint2 bh = *(const uint2*)(W2h + (8 * j + gid) * 72 + t * 16 + tig * 4);
            uint2 bl = *(const uint2*)(W2l + (8 * j + gid) * 72 + t * 16 + tig * 4);
            mma_bf16(C2[0], C2[1], C2[2], C2[3], A2h[t][0], A2h[t][1], A2h[t][2], A2h[t][3], bh.x, bh.y);
            mma_bf16(C2[0], C2[1], C2[2], C2[3], A2h[t][0], A2h[t][1], A2h[t][2], A2h[t][3], bl.x, bl.y);
            mma_bf16(C2[0], C2[1], C2[2], C2[3], A2l[t][0], A2l[t][1], A2l[t][2], A2l[t][3], bh.x, bh.y);
        }
        int c = 8 * j + 2 * tig;
        float2 b2v = *(const float2*)(b2 + c);
        float2 w3v = *(const float2*)(w3 + c);
        partial += fmaxf(C2[0] + b2v.x, 0.f) * w3v.x + fmaxf(C2[1] + b2v.y, 0.f) * w3v.y;
        partial += fmaxf(C2[2] + b2v.x, 0.f) * w3v.x + fmaxf(C2[3] + b2v.y, 0.f) * w3v.y;
    }
    red[tid] = partial;
    __syncthreads();
    for (int st = 64; st > 0; st >>= 1) {
        if (tid < st) red[tid] += red[tid + st];
        __syncthreads();
    }
    if (tid == 0) part[blockIdx.x] = red[0] + 64.f * b3[0];
}

// ------------------------- deterministic final reduction ----------------------
__global__ void reduce_y(const float* __restrict__ part,
                         const float* __restrict__ ob, float* __restrict__ y) {
    int b = threadIdx.x;   // 16
    float s = ob[0];
    #pragma unroll
    for (int i = 0; i < 16; ++i) s += part[b * 16 + i];
    y[b] = s;
}

// ------------------------- launcher ------------------------------------------
extern "C" void kernel_launch(void* const* d_in, const int* in_sizes, int n_in,
                              void* d_out, int out_size) {
    const float* input  = (const float*)d_in[0];
    const float* emb    = (const float*)d_in[1];
    const float* wq     = (const float*)d_in[2];
    const float* wq_b   = (const float*)d_in[3];
    const float* wk     = (const float*)d_in[4];
    const float* wk_b   = (const float*)d_in[5];
    const float* wv     = (const float*)d_in[6];
    const float* wv_b   = (const float*)d_in[7];
    const float* wo     = (const float*)d_in[8];
    const float* ffn_w1 = (const float*)d_in[9];
    const float* ffn_w2 = (const float*)d_in[10];
    const float* ln1_g  = (const float*)d_in[11];
    const float* ln1_b  = (const float*)d_in[12];
    const float* ln2_g  = (const float*)d_in[13];
    const float* ln2_b  = (const float*)d_in[14];
    const float* c_w1   = (const float*)d_in[15];
    const float* c_b1   = (const float*)d_in[16];
    const float* c_w2   = (const float*)d_in[17];
    const float* c_b2   = (const float*)d_in[18];
    const float* c_w3   = (const float*)d_in[19];
    const float* c_b3   = (const float*)d_in[20];
    const float* ob     = (const float*)d_in[21];
    float* y = (float*)d_out;

    float *x, *keep, *nanf, *gbias, *part;
    u16 *ws, *wqkvo, *wcls, *xh, *xl, *cxh, *cxl, *qb, *kbp, *vbp;
    cudaGetSymbolAddress((void**)&x,    g_x);
    cudaGetSymbolAddress((void**)&keep, g_keep);
    cudaGetSymbolAddress((void**)&nanf, g_nanf);
    cudaGetSymbolAddress((void**)&gbias, g_bias);
    cudaGetSymbolAddress((void**)&part, g_part);
    cudaGetSymbolAddress((void**)&ws,   g_ws);
    cudaGetSymbolAddress((void**)&wqkvo, g_wqkvo);
    cudaGetSymbolAddress((void**)&wcls, g_wcls);
    cudaGetSymbolAddress((void**)&xh,   g_xh);
    cudaGetSymbolAddress((void**)&xl,   g_xl);
    cudaGetSymbolAddress((void**)&cxh,  g_cxh);
    cudaGetSymbolAddress((void**)&cxl,  g_cxl);
    cudaGetSymbolAddress((void**)&qb,   g_qb);
    cudaGetSymbolAddress((void**)&kbp,  g_kb);
    cudaGetSymbolAddress((void**)&vbp,  g_vb);

    const int FFN_SMEM = 4 * 64 * 72 * 2;         // 36864 B
    cudaFuncSetAttribute(wo_ffn_kernel, cudaFuncAttributeMaxDynamicSharedMemorySize, FFN_SMEM);

    prep_kernel<<<B_, S_>>>(input, keep, nanf, gbias);
    build_x_kernel<<<(BS * 32) / 256, 256>>>(input, emb, keep, x, xh, xl);
    wprep_all_kernel<<<416, 256>>>(wq, wk, wv, wo, ffn_w1, ffn_w2, c_w1, c_w2,
                                   wqkvo, ws, wcls);

    for (int l = 0; l < L_; ++l) {
        const u16* wqkv_l = wqkvo + (size_t)l * 8 * 4608;       // q,k,v regions
        const u16* wo_l   = wqkvo + ((size_t)l * 8 + 6) * 4608; // o region

        qkv_mma_kernel<<<dim3(BS / 64, 3, 2), 128>>>(
            xh, wqkv_l, wq_b + l * D_, wk_b + l * D_, wv_b + l * D_, qb, kbp, vbp);
        attn_mma_kernel<<<dim3(S_ / 128, B_ * H_), 256>>>(qb, kbp, vbp, gbias, nanf, cxh, cxl);
        wo_ffn_kernel<<<BS / 64, 128, FFN_SMEM>>>(
            cxh, cxl, x, wo_l, ws + (size_t)l * 4 * 4 * 64 * 72,
            ln1_g + l * D_, ln1_b + l * D_, ln2_g + l * D_, ln2_b + l * D_,
            keep, x, xh, xl);
    }

    cls_mma_kernel<<<BS / 64, 128>>>(xh, xl, wcls, c_b1, c_b2, c_w3, c_b3, part);
    reduce_y<<<1, 16>>>(part, ob, y);
}

// round 15
// speedup vs baseline: 1.1755x; 1.1755x over previous
#include <cuda_runtime.h>

#define B_  16
#define S_  1024
#define D_  64
#define H_  4
#define DFF 256
#define L_  2
#define BS  (B_ * S_)

typedef unsigned long long u64;
typedef unsigned int u32;
typedef unsigned short u16;

// ------------------------- device scratch ------------------------------------
__device__ u16   g_qb  [BS * D_];   // q bf16, pre-scaled
__device__ u16   g_kb  [BS * D_];   // k bf16
__device__ u16   g_vb  [BS * D_];   // v bf16
__device__ float g_keep[BS];
__device__ float g_nanf[BS];
__device__ float g_bias[BS];        // 0 or -1e30 per key
__device__ float g_part[BS / 64];
__device__ u16   g_ws   [L_ * 4 * 4 * 64 * 72];  // split ffn weights, frag layout
__device__ u16   g_wqkvo[L_ * 8 * 64 * 72];      // split q,k,v,o weights (hi/lo each)
__device__ u16   g_wcls [4 * 4608];              // split cls w1/w2 (hi/lo each)
__device__ u16   g_xh  [BS * 72];                // x bf16-hi frag layout
__device__ u16   g_xl  [BS * 72];
__device__ u16   g_cxh [BS * 72];                // ctx split frag layout
__device__ u16   g_cxl [BS * 72];

// ------------------------- helpers --------------------------------------------
__device__ __forceinline__ float ex2f(float x) {
    float r; asm("ex2.approx.f32 %0, %1;" : "=f"(r) : "f"(x)); return r;
}
__device__ __forceinline__ u32 bf2(float lo, float hi) {
    u32 r; asm("cvt.rn.bf16x2.f32 %0, %1, %2;" : "=r"(r) : "f"(hi), "f"(lo)); return r;
}
__device__ __forceinline__ u16 bf1(float f) {
    u16 h; asm("cvt.rn.bf16.f32 %0, %1;" : "=h"(h) : "f"(f)); return h;
}
__device__ __forceinline__ float bf16f(u16 h) { return __uint_as_float((u32)h << 16); }
__device__ __forceinline__ float lopart(u32 h) { return __uint_as_float(h << 16); }
__device__ __forceinline__ float hipart(u32 h) { return __uint_as_float(h & 0xffff0000u); }
__device__ __forceinline__ void mma_bf16(
    float& c0, float& c1, float& c2, float& c3,
    u32 a0, u32 a1, u32 a2, u32 a3, u32 b0, u32 b1) {
    asm volatile(
        "mma.sync.aligned.m16n8k16.row.col.f32.bf16.bf16.f32 "
        "{%0,%1,%2,%3},{%4,%5,%6,%7},{%8,%9},{%0,%1,%2,%3};"
        : "+f"(c0), "+f"(c1), "+f"(c2), "+f"(c3)
        : "r"(a0), "r"(a1), "r"(a2), "r"(a3), "r"(b0), "r"(b1));
}
// permuted k-position inside a 16-group
__device__ __forceinline__ int permpos(int j) {   // j in 0..15
    int p = j >> 1, l = j & 1;
    return (p & 3) * 4 + ((p >> 2) << 1) + l;
}
// pos of an even column pair (c,c+1) in the 72-wide frag row
__device__ __forceinline__ int pairpos(int c) {
    int p = (c & 15) >> 1;
    return (c >> 4) * 16 + (p & 3) * 4 + ((p >> 2) << 1);
}
// split a float pair into hi/lo bf16x2
__device__ __forceinline__ void split2(float a, float b, u32& h, u32& l) {
    h = bf2(a, b);
    l = bf2(a - lopart(h), b - hipart(h));
}

// ------------------------- prep: nan flags + keep + bias ----------------------
__global__ void prep_kernel(const float* __restrict__ in,
                            float* __restrict__ keepv, float* __restrict__ nanf,
                            float* __restrict__ gbias) {
    int b = blockIdx.x;
    int s = threadIdx.x;            // 1024 threads
    float v = in[b * S_ + s];
    bool nan = (v != v);
    unsigned bal = __ballot_sync(0xffffffffu, nan);
    __shared__ int warp_all[32];
    __shared__ int allnan_s;
    if ((s & 31) == 0) warp_all[s >> 5] = (bal == 0xffffffffu);
    __syncthreads();
    if (s == 0) {
        int a = 1;
        #pragma unroll
        for (int i = 0; i < 32; ++i) a &= warp_all[i];
        allnan_s = a;
    }
    __syncthreads();
    float kp = (nan || allnan_s) ? 0.f : 1.f;
    keepv[b * S_ + s] = kp;
    nanf [b * S_ + s] = nan ? 1.f : 0.f;
    gbias[b * S_ + s] = nan ? -1e30f : 0.f;
}

// ------------------------- build x (split frag emit only) ---------------------
__global__ void build_x_kernel(const float* __restrict__ in,
                               const float* __restrict__ emb,
                               const float* __restrict__ keepv,
                               u16* __restrict__ xh, u16* __restrict__ xl) {
    int idx = blockIdx.x * 256 + threadIdx.x;   // BS*32
    int cp  = idx & 31;
    int row = idx >> 5;
    int s   = row & (S_ - 1);
    int c   = cp * 2;
    float kp = keepv[row];
    const float SQF = 7.93725393319377f * 8.0f;  // sqrt(63)*sqrt(64)
    float v0 = emb[s * 63 + c] * SQF * kp;
    float v1;
    if (c + 1 == 63) {
        float t = in[row];
        v1 = ((t != t) ? 0.f : t) * kp;
    } else {
        v1 = emb[s * 63 + c + 1] * SQF * kp;
    }
    int pos = pairpos(c);
    u32 h, l; split2(v0, v1, h, l);
    *(u32*)&xh[(size_t)row * 72 + pos] = h;
    *(u32*)&xl[(size_t)row * 72 + pos] = l;
}

// ------------------------- unified weight prep (1 elem/thread) ----------------
// blocks [0,128): qkvo;  [128,384): ffn;  [384,416): cls w1/w2
__global__ void wprep_all_kernel(
    const float* __restrict__ wq, const float* __restrict__ wk,
    const float* __restrict__ wv, const float* __restrict__ wo,
    const float* __restrict__ w1, const float* __restrict__ w2,
    const float* __restrict__ cw1, const float* __restrict__ cw2,
    u16* __restrict__ dstqkvo, u16* __restrict__ ws, u16* __restrict__ wcls) {
    if (blockIdx.x < 128) {
        int idx = blockIdx.x * 256 + threadIdx.x;   // [0, L*4*4096)
        int region = idx >> 12;
        int i      = idx & 4095;
        int l = region >> 2, wsel = region & 3;
        const float* src = (wsel == 0 ? wq : wsel == 1 ? wk : wsel == 2 ? wv : wo) + (size_t)l * 4096;
        u16* dst = dstqkvo + ((size_t)l * 8 + wsel * 2) * 4608;
        int k = i >> 6, n = i & 63;
        int pos = (k >> 4) * 16 + permpos(k & 15);
        float val = src[k * 64 + n];
        u16 h = bf1(val);
        dst[n * 72 + pos]        = h;
        dst[4608 + n * 72 + pos] = bf1(val - bf16f(h));
    } else if (blockIdx.x < 384) {
        int idx = (blockIdx.x - 128) * 256 + threadIdx.x;   // [0, L*4*2*4096)
        int region = idx >> 13;
        int rem    = idx & 8191;
        int which  = rem >> 12;
        int i      = rem & 4095;
        int l = region >> 2, nt = region & 3;
        u16* dst = ws + (size_t)region * (4 * 64 * 72);
        int k = i >> 6, n = i & 63;
        int pos = (k >> 4) * 16 + permpos(k & 15);
        if (which == 0) {
            float wa = w1[(size_t)l * 64 * 256 + k * 256 + nt * 64 + n];
            u16 h = bf1(wa);
            dst[0 * 64 * 72 + n * 72 + pos] = h;
            dst[1 * 64 * 72 + n * 72 + pos] = bf1(wa - bf16f(h));
        } else {
            float wb = w2[(size_t)l * 256 * 64 + (nt * 64 + k) * 64 + n];
            u16 h2 = bf1(wb);
            dst[2 * 64 * 72 + n * 72 + pos] = h2;
            dst[3 * 64 * 72 + n * 72 + pos] = bf1(wb - bf16f(h2));
        }
    } else {
        int idx = (blockIdx.x - 384) * 256 + threadIdx.x;   // [0, 2*4096)
        int which = idx >> 12;
        int i = idx & 4095;
        int k = i >> 6, n = i & 63;
        int pos = (k >> 4) * 16 + permpos(k & 15);
        const float* src = which ? cw2 : cw1;
        u16* dst = wcls + which * 2 * 4608;
        float val = src[k * 64 + n];
        u16 h = bf1(val);
        dst[n * 72 + pos]        = h;
        dst[4608 + n * 72 + pos] = bf1(val - bf16f(h));
    }
}

// ------------------------- tensor-core QKV (hi-only, bf16 out) ----------------
__global__ void __launch_bounds__(128) qkv_mma_kernel(
    const u16* __restrict__ xh,
    const u16* __restrict__ wsplit,   // [3][2][4608] region for this layer
    const float* __restrict__ bq, const float* __restrict__ bk, const float* __restrict__ bv_,
    u16* __restrict__ qb, u16* __restrict__ kb, u16* __restrict__ vb) {
    __shared__ __align__(16) u16 swq[4608];
    int tid = threadIdx.x, w = tid >> 5, lane = tid & 31;
    int gid = lane >> 2, tig = lane & 3;
    int m0 = blockIdx.x * 64;
    int wsel = blockIdx.y;
    int r0 = m0 + w * 16 + gid;

    {   // copy hi weights only (9216 B)
        const float4* src = (const float4*)(wsplit + (size_t)wsel * 2 * 4608);
        float4* dst = (float4*)swq;
        for (int i = tid; i < 576; i += 128) dst[i] = src[i];
    }

    u32 Ah[4][4];
    {
        const u16* ph0 = xh + (size_t)r0 * 72;
        const u16* ph8 = xh + (size_t)(r0 + 8) * 72;
        #pragma unroll
        for (int gk = 0; gk < 4; ++gk) {
            uint2 t0 = *(const uint2*)(ph0 + gk * 16 + tig * 4);
            uint2 t1 = *(const uint2*)(ph8 + gk * 16 + tig * 4);
            Ah[gk][0] = t0.x; Ah[gk][2] = t0.y;
            Ah[gk][1] = t1.x; Ah[gk][3] = t1.y;
        }
    }
    __syncthreads();

    float C2[8][4];
    #pragma unroll
    for (int j = 0; j < 8; ++j)
        #pragma unroll
        for (int i = 0; i < 4; ++i) C2[j][i] = 0.f;

    #pragma unroll
    for (int j = 0; j < 8; ++j) {
        #pragma unroll
        for (int t = 0; t < 4; ++t) {
            uint2 bh = *(const uint2*)(swq + (8 * j + gid) * 72 + t * 16 + tig * 4);
            mma_bf16(C2[j][0], C2[j][1], C2[j][2], C2[j][3],
                     Ah[t][0], Ah[t][1], Ah[t][2], Ah[t][3], bh.x, bh.y);
        }
    }

    const float SC = 0.25f * 1.4426950408889634f;  // applied only to q
    float sc = (wsel == 0) ? SC : 1.f;
    const float* bias = wsel == 0 ? bq : wsel == 1 ? bk : bv_;
    u16* out = wsel == 0 ? qb : wsel == 1 ? kb : vb;
    #pragma unroll
    for (int j = 0; j < 8; ++j) {
        int c = 8 * j + 2 * tig;
        float2 bb = *(const float2*)(bias + c);
        *(u32*)(out + (size_t)r0 * 64 + c)       = bf2((C2[j][0] + bb.x) * sc, (C2[j][1] + bb.y) * sc);
        *(u32*)(out + (size_t)(r0 + 8) * 64 + c) = bf2((C2[j][2] + bb.x) * sc, (C2[j][3] + bb.y) * sc);
    }
}

// ------------------------- tensor-core flash attention (bf16 inputs) ----------
#define KCHUNK 64
__global__ void __launch_bounds__(256) attn_mma_kernel(
    const u16* __restrict__ qb, const u16* __restrict__ kb,
    const u16* __restrict__ vb, const float* __restrict__ gbias,
    const float* __restrict__ nanf,
    u16* __restrict__ cxh, u16* __restrict__ cxl) {
    __shared__ __align__(16) u16 Ks[2][KCHUNK * 18];
    __shared__ __align__(16) u16 Vt[2][16 * 66];
    __shared__ float bias[2][KCHUNK];

    int tid = threadIdx.x;
    int w   = tid >> 5;
    int lane = tid & 31;
    int gid = lane >> 2;
    int tig = lane & 3;
    int bh = blockIdx.y;
    int b = bh >> 2, h = bh & 3;
    int qbase = blockIdx.x * 256;
    size_t bS = (size_t)b * S_;

    int key = tid >> 2, d4 = tid & 3;

    u64 kv0 = *(const u64*)(kb + (bS + key) * 64 + h * 16 + d4 * 4);
    u64 vv0 = *(const u64*)(vb + (bS + key) * 64 + h * 16 + d4 * 4);
    float bb0 = (tid < KCHUNK) ? gbias[bS + tid] : 0.f;

    u32 qa[2][4];
    #pragma unroll
    for (int s = 0; s < 2; ++s) {
        size_t row = bS + qbase + w * 32 + s * 16 + gid;
        qa[s][0] = *(const u32*)(qb + row * 64 + h * 16 + 2 * tig);
        qa[s][1] = *(const u32*)(qb + (row + 8) * 64 + h * 16 + 2 * tig);
        qa[s][2] = *(const u32*)(qb + row * 64 + h * 16 + 8 + 2 * tig);
        qa[s][3] = *(const u32*)(qb + (row + 8) * 64 + h * 16 + 8 + 2 * tig);
    }

    {
        *(u32*)((char*)Ks[0] + key * 36 + d4 * 8)     = (u32)kv0;
        *(u32*)((char*)Ks[0] + key * 36 + d4 * 8 + 4) = (u32)(kv0 >> 32);
        Vt[0][(d4 * 4 + 0) * 66 + key] = (u16)vv0;
        Vt[0][(d4 * 4 + 1) * 66 + key] = (u16)(vv0 >> 16);
        Vt[0][(d4 * 4 + 2) * 66 + key] = (u16)(vv0 >> 32);
        Vt[0][(d4 * 4 + 3) * 66 + key] = (u16)(vv0 >> 48);
        if (tid < KCHUNK) bias[0][tid] = bb0;
    }
    __syncthreads();

    float z[2][2] = {{0.f, 0.f}, {0.f, 0.f}};
    float cd[2][2][4];
    #pragma unroll
    for (int s = 0; s < 2; ++s)
        #pragma unroll
        for (int dt = 0; dt < 2; ++dt)
            #pragma unroll
            for (int i = 0; i < 4; ++i) cd[s][dt][i] = 0.f;

    for (int ch = 0; ch < S_ / KCHUNK; ++ch) {
        int cur = ch & 1;
        u64 kvn = 0, vvn = 0; float bbn = 0.f;
        if (ch + 1 < S_ / KCHUNK) {
            size_t nb = bS + (ch + 1) * KCHUNK;
            kvn = *(const u64*)(kb + (nb + key) * 64 + h * 16 + d4 * 4);
            vvn = *(const u64*)(vb + (nb + key) * 64 + h * 16 + d4 * 4);
            if (tid < KCHUNK) bbn = gbias[nb + tid];
        }

        const u16* KsC = Ks[cur];
        const u16* VtC = Vt[cur];
        const float* biC = bias[cur];

        #pragma unroll
        for (int kbk = 0; kbk < KCHUNK; kbk += 16) {
            u32 kb0a = *(const u32*)((char*)KsC + (kbk + gid) * 36 + tig * 4);
            u32 kb1a = *(const u32*)((char*)KsC + (kbk + gid) * 36 + tig * 4 + 16);
            u32 kb0b = *(const u32*)((char*)KsC + (kbk + 8 + gid) * 36 + tig * 4);
            u32 kb1b = *(const u32*)((char*)KsC + (kbk + 8 + gid) * 36 + tig * 4 + 16);
            u32 vb00 = *(const u32*)((char*)VtC + (gid * 66 + kbk + 2 * tig) * 2);
            u32 vb01 = *(const u32*)((char*)VtC + (gid * 66 + kbk + 8 + 2 * tig) * 2);
            u32 vb10 = *(const u32*)((char*)VtC + ((gid + 8) * 66 + kbk + 2 * tig) * 2);
            u32 vb11 = *(const u32*)((char*)VtC + ((gid + 8) * 66 + kbk + 8 + 2 * tig) * 2);
            float2 bv0 = *(const float2*)(biC + kbk + 2 * tig);
            float2 bv1 = *(const float2*)(biC + kbk + 8 + 2 * tig);

            #pragma unroll
            for (int s = 0; s < 2; ++s) {
                float c0 = bv0.x, c1 = bv0.y, c2 = bv0.x, c3 = bv0.y;
                mma_bf16(c0, c1, c2, c3, qa[s][0], qa[s][1], qa[s][2], qa[s][3], kb0a, kb1a);
                float d0 = bv1.x, d1 = bv1.y, d2 = bv1.x, d3 = bv1.y;
                mma_bf16(d0, d1, d2, d3, qa[s][0], qa[s][1], qa[s][2], qa[s][3], kb0b, kb1b);

                float p0 = ex2f(c0), p1 = ex2f(c1);
                float p2 = ex2f(c2), p3 = ex2f(c3);
                float p4 = ex2f(d0), p5 = ex2f(d1);
                float p6 = ex2f(d2), p7 = ex2f(d3);
                z[s][0] += (p0 + p1) + (p4 + p5);
                z[s][1] += (p2 + p3) + (p6 + p7);

                u32 pa0 = bf2(p0, p1), pa1 = bf2(p2, p3);
                u32 pa2 = bf2(p4, p5), pa3 = bf2(p6, p7);
                mma_bf16(cd[s][0][0], cd[s][0][1], cd[s][0][2], cd[s][0][3],
                         pa0, pa1, pa2, pa3, vb00, vb01);
                mma_bf16(cd[s][1][0], cd[s][1][1], cd[s][1][2], cd[s][1][3],
                         pa0, pa1, pa2, pa3, vb10, vb11);
            }
        }

        if (ch + 1 < S_ / KCHUNK) {
            int nxt = cur ^ 1;
            *(u32*)((char*)Ks[nxt] + key * 36 + d4 * 8)     = (u32)kvn;
            *(u32*)((char*)Ks[nxt] + key * 36 + d4 * 8 + 4) = (u32)(kvn >> 32);
            Vt[nxt][(d4 * 4 + 0) * 66 + key] = (u16)vvn;
            Vt[nxt][(d4 * 4 + 1) * 66 + key] = (u16)(vvn >> 16);
            Vt[nxt][(d4 * 4 + 2) * 66 + key] = (u16)(vvn >> 32);
            Vt[nxt][(d4 * 4 + 3) * 66 + key] = (u16)(vvn >> 48);
            if (tid < KCHUNK) bias[nxt][tid] = bbn;
            __syncthreads();
        }
    }

    int posA = h * 16 + tig * 4;
    int posB = posA + 2;
    #pragma unroll
    for (int s = 0; s < 2; ++s) {
        float z0 = z[s][0], z1 = z[s][1];
        z0 += __shfl_xor_sync(0xffffffffu, z0, 1);
        z0 += __shfl_xor_sync(0xffffffffu, z0, 2);
        z1 += __shfl_xor_sync(0xffffffffu, z1, 1);
        z1 += __shfl_xor_sync(0xffffffffu, z1, 2);

        size_t g0 = bS + qbase + w * 32 + s * 16 + gid;
        size_t g1 = g0 + 8;
        float rk0 = (nanf[g0] == 0.f) ? 1.f : 0.f;
        float rk1 = (nanf[g1] == 0.f) ? 1.f : 0.f;
        float rz0 = (rk0 != 0.f && z0 > 0.f) ? (1.f / z0) : 0.f;
        float rz1 = (rk1 != 0.f && z1 > 0.f) ? (1.f / z1) : 0.f;

        size_t row0 = g0 * 72;
        size_t row1 = g1 * 72;
        u32 hh, ll;
        split2(cd[s][0][0] * rz0, cd[s][0][1] * rz0, hh, ll);
        *(u32*)&cxh[row0 + posA] = hh; *(u32*)&cxl[row0 + posA] = ll;
        split2(cd[s][1][0] * rz0, cd[s][1][1] * rz0, hh, ll);
        *(u32*)&cxh[row0 + posB] = hh; *(u32*)&cxl[row0 + posB] = ll;
        split2(cd[s][0][2] * rz1, cd[s][0][3] * rz1, hh, ll);
        *(u32*)&cxh[row1 + posA] = hh; *(u32*)&cxl[row1 + posA] = ll;
        split2(cd[s][1][2] * rz1, cd[s][1][3] * rz1, hh, ll);
        *(u32*)&cxh[row1 + posB] = hh; *(u32*)&cxl[row1 + posB] = ll;
    }
}

// ------------------------- fused WO + LN1 + FFN + LN2 kernel -------------------
// Residual x comes from xh/xl frag reconstruction (no fp32 x tensor).
__global__ void __launch_bounds__(128) wo_ffn_kernel(
    const u16* __restrict__ cxh, const u16* __restrict__ cxl,
    const u16* __restrict__ wo_w, const u16* __restrict__ ws,
    const float* __restrict__ g1, const float* __restrict__ be1,
    const float* __restrict__ g2, const float* __restrict__ be2,
    const float* __restrict__ keep,
    u16* __restrict__ xh, u16* __restrict__ xl) {
    extern __shared__ u16 sw[];   // 4 * 64 * 72 u16 = 36864 B
    int tid = threadIdx.x, w = tid >> 5, lane = tid & 31;
    int gid = lane >> 2, tig = lane & 3;
    int m0 = blockIdx.x * 64;
    int r0 = m0 + w * 16 + gid;

    float C2[8][4];
    #pragma unroll
    for (int j = 0; j < 8; ++j)
        #pragma unroll
        for (int i = 0; i < 4; ++i) C2[j][i] = 0.f;
    {
        u32 Ah[4][4], Al[4][4];
        const u16* ph0 = cxh + (size_t)r0 * 72;
        const u16* ph8 = cxh + (size_t)(r0 + 8) * 72;
        const u16* pl0 = cxl + (size_t)r0 * 72;
        const u16* pl8 = cxl + (size_t)(r0 + 8) * 72;
        #pragma unroll
        for (int gk = 0; gk < 4; ++gk) {
            uint2 t0 = *(const uint2*)(ph0 + gk * 16 + tig * 4);
            uint2 t1 = *(const uint2*)(ph8 + gk * 16 + tig * 4);
            Ah[gk][0] = t0.x; Ah[gk][2] = t0.y;
            Ah[gk][1] = t1.x; Ah[gk][3] = t1.y;
            uint2 s0 = *(const uint2*)(pl0 + gk * 16 + tig * 4);
            uint2 s1 = *(const uint2*)(pl8 + gk * 16 + tig * 4);
            Al[gk][0] = s0.x; Al[gk][2] = s0.y;
            Al[gk][1] = s1.x; Al[gk][3] = s1.y;
        }
        const u16* Wh = wo_w;
        const u16* Wl = wo_w + 4608;
        #pragma unroll
        for (int j = 0; j < 8; ++j) {
            #pragma unroll
            for (int t = 0; t < 4; ++t) {
                uint2 bh = *(const uint2*)(Wh + (8 * j + gid) * 72 + t * 16 + tig * 4);
                uint2 bl = *(const uint2*)(Wl + (8 * j + gid) * 72 + t * 16 + tig * 4);
                mma_bf16(C2[j][0], C2[j][1], C2[j][2], C2[j][3], Ah[t][0], Ah[t][1], Ah[t][2], Ah[t][3], bh.x, bh.y);
                mma_bf16(C2[j][0], C2[j][1], C2[j][2], C2[j][3], Ah[t][0], Ah[t][1], Ah[t][2], Ah[t][3], bl.x, bl.y);
                mma_bf16(C2[j][0], C2[j][1], C2[j][2], C2[j][3], Al[t][0], Al[t][1], Al[t][2], Al[t][3], bh.x, bh.y);
            }
        }
    }

    float kp0 = keep[r0], kp1 = keep[r0 + 8];

    u32 A1h[4][4], A1l[4][4];
    {
        float v0[16], v1[16];
        float s0 = 0.f, q0 = 0.f, s1 = 0.f, q1 = 0.f;
        #pragma unroll
        for (int j = 0; j < 8; ++j) {
            int c = 8 * j + 2 * tig;
            int pos = pairpos(c);
            u32 xa_h = *(const u32*)&xh[(size_t)r0 * 72 + pos];
            u32 xa_l = *(const u32*)&xl[(size_t)r0 * 72 + pos];
            u32 xb_h = *(const u32*)&xh[(size_t)(r0 + 8) * 72 + pos];
            u32 xb_l = *(const u32*)&xl[(size_t)(r0 + 8) * 72 + pos];
            float a0v = C2[j][0] + (lopart(xa_h) + lopart(xa_l));
            float a1v = C2[j][1] + (hipart(xa_h) + hipart(xa_l));
            float b0v = C2[j][2] + (lopart(xb_h) + lopart(xb_l));
            float b1v = C2[j][3] + (hipart(xb_h) + hipart(xb_l));
            v0[2 * j] = a0v; v0[2 * j + 1] = a1v;
            v1[2 * j] = b0v; v1[2 * j + 1] = b1v;
            s0 += a0v + a1v; q0 += a0v * a0v + a1v * a1v;
            s1 += b0v + b1v; q1 += b0v * b0v + b1v * b1v;
        }
        s0 += __shfl_xor_sync(0xffffffffu, s0, 1); s0 += __shfl_xor_sync(0xffffffffu, s0, 2);
        q0 += __shfl_xor_sync(0xffffffffu, q0, 1); q0 += __shfl_xor_sync(0xffffffffu, q0, 2);
        s1 += __shfl_xor_sync(0xffffffffu, s1, 1); s1 += __shfl_xor_sync(0xffffffffu, s1, 2);
        q1 += __shfl_xor_sync(0xffffffffu, q1, 1); q1 += __shfl_xor_sync(0xffffffffu, q1, 2);
        float m0v = s0 * (1.f / 64.f), m1v = s1 * (1.f / 64.f);
        float i0 = rsqrtf(q0 * (1.f / 64.f) - m0v * m0v + 1e-6f);
        float i1 = rsqrtf(q1 * (1.f / 64.f) - m1v * m1v + 1e-6f);
        #pragma unroll
        for (int j = 0; j < 8; ++j) {
            int c = 8 * j + 2 * tig;
            float2 gg = *(const float2*)(g1 + c);
            float2 bb = *(const float2*)(be1 + c);
            float oax = ((v0[2 * j] - m0v) * i0 * gg.x + bb.x) * kp0;
            float oay = ((v0[2 * j + 1] - m0v) * i0 * gg.y + bb.y) * kp0;
            float obx = ((v1[2 * j] - m1v) * i1 * gg.x + bb.x) * kp1;
            float oby = ((v1[2 * j + 1] - m1v) * i1 * gg.y + bb.y) * kp1;
            int gk = j >> 1, half = (j & 1) << 1;
            split2(oax, oay, A1h[gk][half], A1l[gk][half]);
            split2(obx, oby, A1h[gk][half + 1], A1l[gk][half + 1]);
        }
    }

    #pragma unroll
    for (int j = 0; j < 8; ++j)
        #pragma unroll
        for (int i = 0; i < 4; ++i) C2[j][i] = 0.f;

    for (int nt = 0; nt < 4; ++nt) {
        __syncthreads();
        {
            const float4* src = (const float4*)(ws + (size_t)nt * 4 * 64 * 72);
            float4* dst = (float4*)sw;
            #pragma unroll
            for (int i = 0; i < 18; ++i) dst[tid + i * 128] = src[tid + i * 128];
        }
        __syncthreads();
        const u16* W1h = sw;
        const u16* W1l = sw + 64 * 72;
        const u16* W2h = sw + 2 * 64 * 72;
        const u16* W2l = sw + 3 * 64 * 72;

        u32 A2h[4][4], A2l[4][4];
        #pragma unroll
        for (int t = 0; t < 4; ++t) {
            float Ca[4] = {0.f, 0.f, 0.f, 0.f};
            float Cb[4] = {0.f, 0.f, 0.f, 0.f};
            #pragma unroll
            for (int gk = 0; gk < 4; ++gk) {
                uint2 bha = *(const uint2*)(W1h + (16 * t + gid) * 72 + gk * 16 + tig * 4);
                uint2 bla = *(const uint2*)(W1l + (16 * t + gid) * 72 + gk * 16 + tig * 4);
                mma_bf16(Ca[0], Ca[1], Ca[2], Ca[3], A1h[gk][0], A1h[gk][1], A1h[gk][2], A1h[gk][3], bha.x, bha.y);
                mma_bf16(Ca[0], Ca[1], Ca[2], Ca[3], A1h[gk][0], A1h[gk][1], A1h[gk][2], A1h[gk][3], bla.x, bla.y);
                mma_bf16(Ca[0], Ca[1], Ca[2], Ca[3], A1l[gk][0], A1l[gk][1], A1l[gk][2], A1l[gk][3], bha.x, bha.y);
                uint2 bhb = *(const uint2*)(W1h + (16 * t + 8 + gid) * 72 + gk * 16 + tig * 4);
                uint2 blb = *(const uint2*)(W1l + (16 * t + 8 + gid) * 72 + gk * 16 + tig * 4);
                mma_bf16(Cb[0], Cb[1], Cb[2], Cb[3], A1h[gk][0], A1h[gk][1], A1h[gk][2], A1h[gk][3], bhb.x, bhb.y);
                mma_bf16(Cb[0], Cb[1], Cb[2], Cb[3], A1h[gk][0], A1h[gk][1], A1h[gk][2], A1h[gk][3], blb.x, blb.y);
                mma_bf16(Cb[0], Cb[1], Cb[2], Cb[3], A1l[gk][0], A1l[gk][1], A1l[gk][2], A1l[gk][3], bhb.x, bhb.y);
            }
            #pragma unroll
            for (int i = 0; i < 4; ++i) { Ca[i] = fmaxf(Ca[i], 0.f); Cb[i] = fmaxf(Cb[i], 0.f); }
            split2(Ca[0], Ca[1], A2h[t][0], A2l[t][0]);
            split2(Ca[2], Ca[3], A2h[t][1], A2l[t][1]);
            split2(Cb[0], Cb[1], A2h[t][2], A2l[t][2]);
            split2(Cb[2], Cb[3], A2h[t][3], A2l[t][3]);
        }

        #pragma unroll
        for (int j = 0; j < 8; ++j) {
            #pragma unroll
            for (int t = 0; t < 4; ++t) {
                uint2 bh = *(const uint2*)(W2h + (8 * j + gid) * 72 + t * 16 + tig * 4);
                uint2 bl = *(const uint2*)(W2l + (8 * j + gid) * 72 + t * 16 + tig * 4);
                mma_bf16(C2[j][0], C2[j][1], C2[j][2], C2[j][3], A2h[t][0], A2h[t][1], A2h[t][2], A2h[t][3], bh.x, bh.y);
                mma_bf16(C2[j][0], C2[j][1], C2[j][2], C2[j][3], A2h[t][0], A2h[t][1], A2h[t][2], A2h[t][3], bl.x, bl.y);
                mma_bf16(C2[j][0], C2[j][1], C2[j][2], C2[j][3], A2l[t][0], A2l[t][1], A2l[t][2], A2l[t][3], bh.x, bh.y);
            }
        }
    }

    float v0[16], v1[16];
    float s0 = 0.f, q0 = 0.f, s1 = 0.f, q1 = 0.f;
    #pragma unroll
    for (int j = 0; j < 8; ++j) {
        int gk = j >> 1, half = (j & 1) << 1;
        float rax = lopart(A1h[gk][half])     + lopart(A1l[gk][half]);
        float ray = hipart(A1h[gk][half])     + hipart(A1l[gk][half]);
        float rbx = lopart(A1h[gk][half + 1]) + lopart(A1l[gk][half + 1]);
        float rby = hipart(A1h[gk][half + 1]) + hipart(A1l[gk][half + 1]);
        float a0v = C2[j][0] + rax, a1v = C2[j][1] + ray;
        float b0v = C2[j][2] + rbx, b1v = C2[j][3] + rby;
        v0[2 * j] = a0v; v0[2 * j + 1] = a1v;
        v1[2 * j] = b0v; v1[2 * j + 1] = b1v;
        s0 += a0v + a1v; q0 += a0v * a0v + a1v * a1v;
        s1 += b0v + b1v; q1 += b0v * b0v + b1v * b1v;
    }
    s0 += __shfl_xor_sync(0xffffffffu, s0, 1); s0 += __shfl_xor_sync(0xffffffffu, s0, 2);
    q0 += __shfl_xor_sync(0xffffffffu, q0, 1); q0 += __shfl_xor_sync(0xffffffffu, q0, 2);
    s1 += __shfl_xor_sync(0xffffffffu, s1, 1); s1 += __shfl_xor_sync(0xffffffffu, s1, 2);
    q1 += __shfl_xor_sync(0xffffffffu, q1, 1); q1 += __shfl_xor_sync(0xffffffffu, q1, 2);
    float m0v = s0 * (1.f / 64.f), m1v = s1 * (1.f / 64.f);
    float i0 = rsqrtf(q0 * (1.f / 64.f) - m0v * m0v + 1e-6f);
    float i1 = rsqrtf(q1 * (1.f / 64.f) - m1v * m1v + 1e-6f);
    #pragma unroll
    for (int j = 0; j < 8; ++j) {
        int c = 8 * j + 2 * tig;
        float2 gg = *(const float2*)(g2 + c);
        float2 bb = *(const float2*)(be2 + c);
        float oax = ((v0[2 * j] - m0v) * i0 * gg.x + bb.x) * kp0;
        float oay = ((v0[2 * j + 1] - m0v) * i0 * gg.y + bb.y) * kp0;
        float obx = ((v1[2 * j] - m1v) * i1 * gg.x + bb.x) * kp1;
        float oby = ((v1[2 * j + 1] - m1v) * i1 * gg.y + bb.y) * kp1;
        int pos = pairpos(c);
        u32 hh, ll;
        split2(oax, oay, hh, ll);
        *(u32*)&xh[(size_t)r0 * 72 + pos] = hh; *(u32*)&xl[(size_t)r0 * 72 + pos] = ll;
        split2(obx, oby, hh, ll);
        *(u32*)&xh[(size_t)(r0 + 8) * 72 + pos] = hh; *(u32*)&xl[(size_t)(r0 + 8) * 72 + pos] = ll;
    }
}

// ------------------------- tensor-core classifier ------------------------------
__global__ void __launch_bounds__(128) cls_mma_kernel(
    const u16* __restrict__ xh, const u16* __restrict__ xl,
    const u16* __restrict__ wcls,   // [w1h|w1l|w2h|w2l], each 4608 u16
    const float* __restrict__ b1, const float* __restrict__ b2,
    const float* __restrict__ w3, const float* __restrict__ b3,
    float* __restrict__ part) {
    __shared__ __align__(16) u16 sw[4 * 4608];   // 36864 B
    __shared__ float red[128];
    int tid = threadIdx.x, w = tid >> 5, lane = tid & 31;
    int gid = lane >> 2, tig = lane & 3;
    int m0 = blockIdx.x * 64;
    int r0 = m0 + w * 16 + gid;

    {
        const float4* src = (const float4*)wcls;
        float4* dst = (float4*)sw;
        #pragma unroll
        for (int i = 0; i < 18; ++i) dst[tid + i * 128] = src[tid + i * 128];
    }

    u32 Ah[4][4], Al[4][4];
    {
        const u16* ph0 = xh + (size_t)r0 * 72;
        const u16* ph8 = xh + (size_t)(r0 + 8) * 72;
        const u16* pl0 = xl + (size_t)r0 * 72;
        const u16* pl8 = xl + (size_t)(r0 + 8) * 72;
        #pragma unroll
        for (int gk = 0; gk < 4; ++gk) {
            uint2 t0 = *(const uint2*)(ph0 + gk * 16 + tig * 4);
            uint2 t1 = *(const uint2*)(ph8 + gk * 16 + tig * 4);
            Ah[gk][0] = t0.x; Ah[gk][2] = t0.y;
            Ah[gk][1] = t1.x; Ah[gk][3] = t1.y;
            uint2 s0 = *(const uint2*)(pl0 + gk * 16 + tig * 4);
            uint2 s1 = *(const uint2*)(pl8 + gk * 16 + tig * 4);
            Al[gk][0] = s0.x; Al[gk][2] = s0.y;
            Al[gk][1] = s1.x; Al[gk][3] = s1.y;
        }
    }
    __syncthreads();
    const u16* W1h = sw;
    const u16* W1l = sw + 4608;
    const u16* W2h = sw + 2 * 4608;
    const u16* W2l = sw + 3 * 4608;

    u32 A2h[4][4], A2l[4][4];
    #pragma unroll
    for (int t = 0; t < 4; ++t) {
        float Ca[4] = {0.f, 0.f, 0.f, 0.f};
        float Cb[4] = {0.f, 0.f, 0.f, 0.f};
        #pragma unroll
        for (int gk = 0; gk < 4; ++gk) {
            uint2 bha = *(const uint2*)(W1h + (16 * t + gid) * 72 + gk * 16 + tig * 4);
            uint2 bla = *(const uint2*)(W1l + (16 * t + gid) * 72 + gk * 16 + tig * 4);
            mma_bf16(Ca[0], Ca[1], Ca[2], Ca[3], Ah[gk][0], Ah[gk][1], Ah[gk][2], Ah[gk][3], bha.x, bha.y);
            mma_bf16(Ca[0], Ca[1], Ca[2], Ca[3], Ah[gk][0], Ah[gk][1], Ah[gk][2], Ah[gk][3], bla.x, bla.y);
            mma_bf16(Ca[0], Ca[1], Ca[2], Ca[3], Al[gk][0], Al[gk][1], Al[gk][2], Al[gk][3], bha.x, bha.y);
            uint2 bhb = *(const uint2*)(W1h + (16 * t + 8 + gid) * 72 + gk * 16 + tig * 4);
            uint2 blb = *(const uint2*)(W1l + (16 * t + 8 + gid) * 72 + gk * 16 + tig * 4);
            mma_bf16(Cb[0], Cb[1], Cb[2], Cb[3], Ah[gk][0], Ah[gk][1], Ah[gk][2], Ah[gk][3], bhb.x, bhb.y);
            mma_bf16(Cb[0], Cb[1], Cb[2], Cb[3], Ah[gk][0], Ah[gk][1], Ah[gk][2], Ah[gk][3], blb.x, blb.y);
            mma_bf16(Cb[0], Cb[1], Cb[2], Cb[3], Al[gk][0], Al[gk][1], Al[gk][2], Al[gk][3], bhb.x, bhb.y);
        }
        float2 b1a = *(const float2*)(b1 + 16 * t + 2 * tig);
        float2 b1b = *(const float2*)(b1 + 16 * t + 8 + 2 * tig);
        Ca[0] = fmaxf(Ca[0] + b1a.x, 0.f); Ca[1] = fmaxf(Ca[1] + b1a.y, 0.f);
        Ca[2] = fmaxf(Ca[2] + b1a.x, 0.f); Ca[3] = fmaxf(Ca[3] + b1a.y, 0.f);
        Cb[0] = fmaxf(Cb[0] + b1b.x, 0.f); Cb[1] = fmaxf(Cb[1] + b1b.y, 0.f);
        Cb[2] = fmaxf(Cb[2] + b1b.x, 0.f); Cb[3] = fmaxf(Cb[3] + b1b.y, 0.f);
        split2(Ca[0], Ca[1], A2h[t][0], A2l[t][0]);
        split2(Ca[2], Ca[3], A2h[t][1], A2l[t][1]);
        split2(Cb[0], Cb[1], A2h[t][2], A2l[t][2]);
        split2(Cb[2], Cb[3], A2h[t][3], A2l[t][3]);
    }

    float partial = 0.f;
    #pragma unroll
    for (int j = 0; j < 8; ++j) {
        float C2[4] = {0.f, 0.f, 0.f, 0.f};
        #pragma unroll
        for (int t = 0; t < 4; ++t) {
            uint2 bh = *(const uint2*)(W2h + (8 * j + gid) * 72 + t * 16 + tig * 4);
            uint2 bl = *(const uint2*)(W2l + (8 * j + gid) * 72 + t * 16 + tig * 4);
            mma_bf16(C2[0], C2[1], C2[2], C2[3], A2h[t][0], A2h[t][1], A2h[t][2], A2h[t][3], bh.x, bh.y);
            mma_bf16(C2[0], C2[1], C2[2], C2[3], A2h[t][0], A2h[t][1], A2h[t][2], A2h[t][3], bl.x, bl.y);
            mma_bf16(C2[0], C2[1], C2[2], C2[3], A2l[t][0], A2l[t][1], A2l[t][2], A2l[t][3], bh.x, bh.y);
        }
        int c = 8 * j + 2 * tig;
        float2 b2v = *(const float2*)(b2 + c);
        float2 w3v = *(const float2*)(w3 + c);
        partial += fmaxf(C2[0] + b2v.x, 0.f) * w3v.x + fmaxf(C2[1] + b2v.y, 0.f) * w3v.y;
        partial += fmaxf(C2[2] + b2v.x, 0.f) * w3v.x + fmaxf(C2[3] + b2v.y, 0.f) * w3v.y;
    }
    red[tid] = partial;
    __syncthreads();
    for (int st = 64; st > 0; st >>= 1) {
        if (tid < st) red[tid] += red[tid + st];
        __syncthreads();
    }
    if (tid == 0) part[blockIdx.x] = red[0] + 64.f * b3[0];
}

// ------------------------- deterministic final reduction ----------------------
__global__ void reduce_y(const float* __restrict__ part,
                         const float* __restrict__ ob, float* __restrict__ y) {
    int b = threadIdx.x;   // 16
    float s = ob[0];
    #pragma unroll
    for (int i = 0; i < 16; ++i) s += part[b * 16 + i];
    y[b] = s;
}

// ------------------------- launcher ------------------------------------------
extern "C" void kernel_launch(void* const* d_in, const int* in_sizes, int n_in,
                              void* d_out, int out_size) {
    const float* input  = (const float*)d_in[0];
    const float* emb    = (const float*)d_in[1];
    const float* wq     = (const float*)d_in[2];
    const float* wq_b   = (const float*)d_in[3];
    const float* wk     = (const float*)d_in[4];
    const float* wk_b   = (const float*)d_in[5];
    const float* wv     = (const float*)d_in[6];
    const float* wv_b   = (const float*)d_in[7];
    const float* wo     = (const float*)d_in[8];
    const float* ffn_w1 = (const float*)d_in[9];
    const float* ffn_w2 = (const float*)d_in[10];
    const float* ln1_g  = (const float*)d_in[11];
    const float* ln1_b  = (const float*)d_in[12];
    const float* ln2_g  = (const float*)d_in[13];
    const float* ln2_b  = (const float*)d_in[14];
    const float* c_w1   = (const float*)d_in[15];
    const float* c_b1   = (const float*)d_in[16];
    const float* c_w2   = (const float*)d_in[17];
    const float* c_b2   = (const float*)d_in[18];
    const float* c_w3   = (const float*)d_in[19];
    const float* c_b3   = (const float*)d_in[20];
    const float* ob     = (const float*)d_in[21];
    float* y = (float*)d_out;

    float *keep, *nanf, *gbias, *part;
    u16 *ws, *wqkvo, *wcls, *xh, *xl, *cxh, *cxl, *qb, *kbp, *vbp;
    cudaGetSymbolAddress((void**)&keep, g_keep);
    cudaGetSymbolAddress((void**)&nanf, g_nanf);
    cudaGetSymbolAddress((void**)&gbias, g_bias);
    cudaGetSymbolAddress((void**)&part, g_part);
    cudaGetSymbolAddress((void**)&ws,   g_ws);
    cudaGetSymbolAddress((void**)&wqkvo, g_wqkvo);
    cudaGetSymbolAddress((void**)&wcls, g_wcls);
    cudaGetSymbolAddress((void**)&xh,   g_xh);
    cudaGetSymbolAddress((void**)&xl,   g_xl);
    cudaGetSymbolAddress((void**)&cxh,  g_cxh);
    cudaGetSymbolAddress((void**)&cxl,  g_cxl);
    cudaGetSymbolAddress((void**)&qb,   g_qb);
    cudaGetSymbolAddress((void**)&kbp,  g_kb);
    cudaGetSymbolAddress((void**)&vbp,  g_vb);

    const int FFN_SMEM = 4 * 64 * 72 * 2;         // 36864 B
    cudaFuncSetAttribute(wo_ffn_kernel, cudaFuncAttributeMaxDynamicSharedMemorySize, FFN_SMEM);

    prep_kernel<<<B_, S_>>>(input, keep, nanf, gbias);
    build_x_kernel<<<(BS * 32) / 256, 256>>>(input, emb, keep, xh, xl);
    wprep_all_kernel<<<416, 256>>>(wq, wk, wv, wo, ffn_w1, ffn_w2, c_w1, c_w2,
                                   wqkvo, ws, wcls);

    for (int l = 0; l < L_; ++l) {
        const u16* wqkv_l = wqkvo + (size_t)l * 8 * 4608;       // q,k,v regions
        const u16* wo_l   = wqkvo + ((size_t)l * 8 + 6) * 4608; // o region

        qkv_mma_kernel<<<dim3(BS / 64, 3), 128>>>(
            xh, wqkv_l, wq_b + l * D_, wk_b + l * D_, wv_b + l * D_, qb, kbp, vbp);
        attn_mma_kernel<<<dim3(S_ / 256, B_ * H_), 256>>>(qb, kbp, vbp, gbias, nanf, cxh, cxl);
        wo_ffn_kernel<<<BS / 64, 128, FFN_SMEM>>>(
            cxh, cxl, wo_l, ws + (size_t)l * 4 * 4 * 64 * 72,
            ln1_g + l * D_, ln1_b + l * D_, ln2_g + l * D_, ln2_b + l * D_,
            keep, xh, xl);
    }

    cls_mma_kernel<<<BS / 64, 128>>>(xh, xl, wcls, c_b1, c_b2, c_w3, c_b3, part);
    reduce_y<<<1, 16>>>(part, ob, y);
}

// round 16
// speedup vs baseline: 1.1757x; 1.0002x over previous
#include <cuda_runtime.h>

#define B_  16
#define S_  1024
#define D_  64
#define H_  4
#define DFF 256
#define L_  2
#define BS  (B_ * S_)

typedef unsigned long long u64;
typedef unsigned int u32;
typedef unsigned short u16;

// ------------------------- device scratch ------------------------------------
__device__ u16   g_qb  [BS * D_];   // q bf16, pre-scaled
__device__ u16   g_kb  [BS * D_];   // k bf16
__device__ u16   g_vb  [BS * D_];   // v bf16
__device__ float g_keep[BS];
__device__ float g_nanf[BS];
__device__ float g_bias[BS];        // 0 or -1e30 per key
__device__ float g_part[BS / 64];
__device__ u16   g_ws   [L_ * 4 * 4 * 64 * 72];  // split ffn weights, frag layout
__device__ u16   g_wqkvo[L_ * 8 * 64 * 72];      // split q,k,v,o weights (hi/lo each)
__device__ u16   g_wcls [4 * 4608];              // split cls w1/w2 (hi/lo each)
__device__ u16   g_xh  [BS * 72];                // x bf16-hi frag layout
__device__ u16   g_xl  [BS * 72];
__device__ u16   g_cxh [BS * 72];                // ctx split frag layout
__device__ u16   g_cxl [BS * 72];

// ------------------------- helpers --------------------------------------------
__device__ __forceinline__ float ex2f(float x) {
    float r; asm("ex2.approx.f32 %0, %1;" : "=f"(r) : "f"(x)); return r;
}
__device__ __forceinline__ u32 bf2(float lo, float hi) {
    u32 r; asm("cvt.rn.bf16x2.f32 %0, %1, %2;" : "=r"(r) : "f"(hi), "f"(lo)); return r;
}
__device__ __forceinline__ u16 bf1(float f) {
    u16 h; asm("cvt.rn.bf16.f32 %0, %1;" : "=h"(h) : "f"(f)); return h;
}
__device__ __forceinline__ float bf16f(u16 h) { return __uint_as_float((u32)h << 16); }
__device__ __forceinline__ float lopart(u32 h) { return __uint_as_float(h << 16); }
__device__ __forceinline__ float hipart(u32 h) { return __uint_as_float(h & 0xffff0000u); }
__device__ __forceinline__ void mma_bf16(
    float& c0, float& c1, float& c2, float& c3,
    u32 a0, u32 a1, u32 a2, u32 a3, u32 b0, u32 b1) {
    asm volatile(
        "mma.sync.aligned.m16n8k16.row.col.f32.bf16.bf16.f32 "
        "{%0,%1,%2,%3},{%4,%5,%6,%7},{%8,%9},{%0,%1,%2,%3};"
        : "+f"(c0), "+f"(c1), "+f"(c2), "+f"(c3)
        : "r"(a0), "r"(a1), "r"(a2), "r"(a3), "r"(b0), "r"(b1));
}
// permuted k-position inside a 16-group
__device__ __forceinline__ int permpos(int j) {   // j in 0..15
    int p = j >> 1, l = j & 1;
    return (p & 3) * 4 + ((p >> 2) << 1) + l;
}
// pos of an even column pair (c,c+1) in the 72-wide frag row
__device__ __forceinline__ int pairpos(int c) {
    int p = (c & 15) >> 1;
    return (c >> 4) * 16 + (p & 3) * 4 + ((p >> 2) << 1);
}
// split a float pair into hi/lo bf16x2
__device__ __forceinline__ void split2(float a, float b, u32& h, u32& l) {
    h = bf2(a, b);
    l = bf2(a - lopart(h), b - hipart(h));
}

// ------------------------- prep: nan flags + keep + bias ----------------------
__global__ void prep_kernel(const float* __restrict__ in,
                            float* __restrict__ keepv, float* __restrict__ nanf,
                            float* __restrict__ gbias) {
    int b = blockIdx.x;
    int s = threadIdx.x;            // 1024 threads
    float v = in[b * S_ + s];
    bool nan = (v != v);
    unsigned bal = __ballot_sync(0xffffffffu, nan);
    __shared__ int warp_all[32];
    __shared__ int allnan_s;
    if ((s & 31) == 0) warp_all[s >> 5] = (bal == 0xffffffffu);
    __syncthreads();
    if (s == 0) {
        int a = 1;
        #pragma unroll
        for (int i = 0; i < 32; ++i) a &= warp_all[i];
        allnan_s = a;
    }
    __syncthreads();
    float kp = (nan || allnan_s) ? 0.f : 1.f;
    keepv[b * S_ + s] = kp;
    nanf [b * S_ + s] = nan ? 1.f : 0.f;
    gbias[b * S_ + s] = nan ? -1e30f : 0.f;
}

// ------------------------- build x (split frag emit only) ---------------------
__global__ void build_x_kernel(const float* __restrict__ in,
                               const float* __restrict__ emb,
                               const float* __restrict__ keepv,
                               u16* __restrict__ xh, u16* __restrict__ xl) {
    int idx = blockIdx.x * 256 + threadIdx.x;   // BS*32
    int cp  = idx & 31;
    int row = idx >> 5;
    int s   = row & (S_ - 1);
    int c   = cp * 2;
    float kp = keepv[row];
    const float SQF = 7.93725393319377f * 8.0f;  // sqrt(63)*sqrt(64)
    float v0 = emb[s * 63 + c] * SQF * kp;
    float v1;
    if (c + 1 == 63) {
        float t = in[row];
        v1 = ((t != t) ? 0.f : t) * kp;
    } else {
        v1 = emb[s * 63 + c + 1] * SQF * kp;
    }
    int pos = pairpos(c);
    u32 h, l; split2(v0, v1, h, l);
    *(u32*)&xh[(size_t)row * 72 + pos] = h;
    *(u32*)&xl[(size_t)row * 72 + pos] = l;
}

// ------------------------- unified weight prep (1 elem/thread) ----------------
// blocks [0,128): qkvo;  [128,384): ffn;  [384,416): cls w1/w2
__global__ void wprep_all_kernel(
    const float* __restrict__ wq, const float* __restrict__ wk,
    const float* __restrict__ wv, const float* __restrict__ wo,
    const float* __restrict__ w1, const float* __restrict__ w2,
    const float* __restrict__ cw1, const float* __restrict__ cw2,
    u16* __restrict__ dstqkvo, u16* __restrict__ ws, u16* __restrict__ wcls) {
    if (blockIdx.x < 128) {
        int idx = blockIdx.x * 256 + threadIdx.x;   // [0, L*4*4096)
        int region = idx >> 12;
        int i      = idx & 4095;
        int l = region >> 2, wsel = region & 3;
        const float* src = (wsel == 0 ? wq : wsel == 1 ? wk : wsel == 2 ? wv : wo) + (size_t)l * 4096;
        u16* dst = dstqkvo + ((size_t)l * 8 + wsel * 2) * 4608;
        int k = i >> 6, n = i & 63;
        int pos = (k >> 4) * 16 + permpos(k & 15);
        float val = src[k * 64 + n];
        u16 h = bf1(val);
        dst[n * 72 + pos]        = h;
        dst[4608 + n * 72 + pos] = bf1(val - bf16f(h));
    } else if (blockIdx.x < 384) {
        int idx = (blockIdx.x - 128) * 256 + threadIdx.x;   // [0, L*4*2*4096)
        int region = idx >> 13;
        int rem    = idx & 8191;
        int which  = rem >> 12;
        int i      = rem & 4095;
        int l = region >> 2, nt = region & 3;
        u16* dst = ws + (size_t)region * (4 * 64 * 72);
        int k = i >> 6, n = i & 63;
        int pos = (k >> 4) * 16 + permpos(k & 15);
        if (which == 0) {
            float wa = w1[(size_t)l * 64 * 256 + k * 256 + nt * 64 + n];
            u16 h = bf1(wa);
            dst[0 * 64 * 72 + n * 72 + pos] = h;
            dst[1 * 64 * 72 + n * 72 + pos] = bf1(wa - bf16f(h));
        } else {
            float wb = w2[(size_t)l * 256 * 64 + (nt * 64 + k) * 64 + n];
            u16 h2 = bf1(wb);
            dst[2 * 64 * 72 + n * 72 + pos] = h2;
            dst[3 * 64 * 72 + n * 72 + pos] = bf1(wb - bf16f(h2));
        }
    } else {
        int idx = (blockIdx.x - 384) * 256 + threadIdx.x;   // [0, 2*4096)
        int which = idx >> 12;
        int i = idx & 4095;
        int k = i >> 6, n = i & 63;
        int pos = (k >> 4) * 16 + permpos(k & 15);
        const float* src = which ? cw2 : cw1;
        u16* dst = wcls + which * 2 * 4608;
        float val = src[k * 64 + n];
        u16 h = bf1(val);
        dst[n * 72 + pos]        = h;
        dst[4608 + n * 72 + pos] = bf1(val - bf16f(h));
    }
}

// ------------------------- tensor-core QKV (hi-only, bf16 out) ----------------
__global__ void __launch_bounds__(128) qkv_mma_kernel(
    const u16* __restrict__ xh,
    const u16* __restrict__ wsplit,   // [3][2][4608] region for this layer
    const float* __restrict__ bq, const float* __restrict__ bk, const float* __restrict__ bv_,
    u16* __restrict__ qb, u16* __restrict__ kb, u16* __restrict__ vb) {
    __shared__ __align__(16) u16 swq[4608];
    int tid = threadIdx.x, w = tid >> 5, lane = tid & 31;
    int gid = lane >> 2, tig = lane & 3;
    int m0 = blockIdx.x * 64;
    int wsel = blockIdx.y;
    int r0 = m0 + w * 16 + gid;

    {   // copy hi weights only (9216 B)
        const float4* src = (const float4*)(wsplit + (size_t)wsel * 2 * 4608);
        float4* dst = (float4*)swq;
        for (int i = tid; i < 576; i += 128) dst[i] = src[i];
    }

    u32 Ah[4][4];
    {
        const u16* ph0 = xh + (size_t)r0 * 72;
        const u16* ph8 = xh + (size_t)(r0 + 8) * 72;
        #pragma unroll
        for (int gk = 0; gk < 4; ++gk) {
            uint2 t0 = *(const uint2*)(ph0 + gk * 16 + tig * 4);
            uint2 t1 = *(const uint2*)(ph8 + gk * 16 + tig * 4);
            Ah[gk][0] = t0.x; Ah[gk][2] = t0.y;
            Ah[gk][1] = t1.x; Ah[gk][3] = t1.y;
        }
    }
    __syncthreads();

    float C2[8][4];
    #pragma unroll
    for (int j = 0; j < 8; ++j)
        #pragma unroll
        for (int i = 0; i < 4; ++i) C2[j][i] = 0.f;

    #pragma unroll
    for (int j = 0; j < 8; ++j) {
        #pragma unroll
        for (int t = 0; t < 4; ++t) {
            uint2 bh = *(const uint2*)(swq + (8 * j + gid) * 72 + t * 16 + tig * 4);
            mma_bf16(C2[j][0], C2[j][1], C2[j][2], C2[j][3],
                     Ah[t][0], Ah[t][1], Ah[t][2], Ah[t][3], bh.x, bh.y);
        }
    }

    const float SC = 0.25f * 1.4426950408889634f;  // applied only to q
    float sc = (wsel == 0) ? SC : 1.f;
    const float* bias = wsel == 0 ? bq : wsel == 1 ? bk : bv_;
    u16* out = wsel == 0 ? qb : wsel == 1 ? kb : vb;
    #pragma unroll
    for (int j = 0; j < 8; ++j) {
        int c = 8 * j + 2 * tig;
        float2 bb = *(const float2*)(bias + c);
        *(u32*)(out + (size_t)r0 * 64 + c)       = bf2((C2[j][0] + bb.x) * sc, (C2[j][1] + bb.y) * sc);
        *(u32*)(out + (size_t)(r0 + 8) * 64 + c) = bf2((C2[j][2] + bb.x) * sc, (C2[j][3] + bb.y) * sc);
    }
}

// ------------------------- tensor-core flash attention (bf16 inputs) ----------
#define KCHUNK 64
__global__ void __launch_bounds__(256) attn_mma_kernel(
    const u16* __restrict__ qb, const u16* __restrict__ kb,
    const u16* __restrict__ vb, const float* __restrict__ gbias,
    const float* __restrict__ nanf,
    u16* __restrict__ cxh, u16* __restrict__ cxl) {
    __shared__ __align__(16) u16 Ks[2][KCHUNK * 18];
    __shared__ __align__(16) u16 Vt[2][16 * 66];
    __shared__ float bias[2][KCHUNK];

    int tid = threadIdx.x;
    int w   = tid >> 5;
    int lane = tid & 31;
    int gid = lane >> 2;
    int tig = lane & 3;
    int bh = blockIdx.y;
    int b = bh >> 2, h = bh & 3;
    int qbase = blockIdx.x * 256;
    size_t bS = (size_t)b * S_;

    int key = tid >> 2, d4 = tid & 3;

    u64 kv0 = *(const u64*)(kb + (bS + key) * 64 + h * 16 + d4 * 4);
    u64 vv0 = *(const u64*)(vb + (bS + key) * 64 + h * 16 + d4 * 4);
    float bb0 = (tid < KCHUNK) ? gbias[bS + tid] : 0.f;

    u32 qa[2][4];
    #pragma unroll
    for (int s = 0; s < 2; ++s) {
        size_t row = bS + qbase + w * 32 + s * 16 + gid;
        qa[s][0] = *(const u32*)(qb + row * 64 + h * 16 + 2 * tig);
        qa[s][1] = *(const u32*)(qb + (row + 8) * 64 + h * 16 + 2 * tig);
        qa[s][2] = *(const u32*)(qb + row * 64 + h * 16 + 8 + 2 * tig);
        qa[s][3] = *(const u32*)(qb + (row + 8) * 64 + h * 16 + 8 + 2 * tig);
    }

    {
        *(u32*)((char*)Ks[0] + key * 36 + d4 * 8)     = (u32)kv0;
        *(u32*)((char*)Ks[0] + key * 36 + d4 * 8 + 4) = (u32)(kv0 >> 32);
        Vt[0][(d4 * 4 + 0) * 66 + key] = (u16)vv0;
        Vt[0][(d4 * 4 + 1) * 66 + key] = (u16)(vv0 >> 16);
        Vt[0][(d4 * 4 + 2) * 66 + key] = (u16)(vv0 >> 32);
        Vt[0][(d4 * 4 + 3) * 66 + key] = (u16)(vv0 >> 48);
        if (tid < KCHUNK) bias[0][tid] = bb0;
    }
    __syncthreads();

    float z[2][2] = {{0.f, 0.f}, {0.f, 0.f}};
    float cd[2][2][4];
    #pragma unroll
    for (int s = 0; s < 2; ++s)
        #pragma unroll
        for (int dt = 0; dt < 2; ++dt)
            #pragma unroll
            for (int i = 0; i < 4; ++i) cd[s][dt][i] = 0.f;

    for (int ch = 0; ch < S_ / KCHUNK; ++ch) {
        int cur = ch & 1;
        u64 kvn = 0, vvn = 0; float bbn = 0.f;
        if (ch + 1 < S_ / KCHUNK) {
            size_t nb = bS + (ch + 1) * KCHUNK;
            kvn = *(const u64*)(kb + (nb + key) * 64 + h * 16 + d4 * 4);
            vvn = *(const u64*)(vb + (nb + key) * 64 + h * 16 + d4 * 4);
            if (tid < KCHUNK) bbn = gbias[nb + tid];
        }

        const u16* KsC = Ks[cur];
        const u16* VtC = Vt[cur];
        const float* biC = bias[cur];

        #pragma unroll
        for (int kbk = 0; kbk < KCHUNK; kbk += 16) {
            u32 kb0a = *(const u32*)((char*)KsC + (kbk + gid) * 36 + tig * 4);
            u32 kb1a = *(const u32*)((char*)KsC + (kbk + gid) * 36 + tig * 4 + 16);
            u32 kb0b = *(const u32*)((char*)KsC + (kbk + 8 + gid) * 36 + tig * 4);
            u32 kb1b = *(const u32*)((char*)KsC + (kbk + 8 + gid) * 36 + tig * 4 + 16);
            u32 vb00 = *(const u32*)((char*)VtC + (gid * 66 + kbk + 2 * tig) * 2);
            u32 vb01 = *(const u32*)((char*)VtC + (gid * 66 + kbk + 8 + 2 * tig) * 2);
            u32 vb10 = *(const u32*)((char*)VtC + ((gid + 8) * 66 + kbk + 2 * tig) * 2);
            u32 vb11 = *(const u32*)((char*)VtC + ((gid + 8) * 66 + kbk + 8 + 2 * tig) * 2);
            float2 bv0 = *(const float2*)(biC + kbk + 2 * tig);
            float2 bv1 = *(const float2*)(biC + kbk + 8 + 2 * tig);

            #pragma unroll
            for (int s = 0; s < 2; ++s) {
                float c0 = bv0.x, c1 = bv0.y, c2 = bv0.x, c3 = bv0.y;
                mma_bf16(c0, c1, c2, c3, qa[s][0], qa[s][1], qa[s][2], qa[s][3], kb0a, kb1a);
                float d0 = bv1.x, d1 = bv1.y, d2 = bv1.x, d3 = bv1.y;
                mma_bf16(d0, d1, d2, d3, qa[s][0], qa[s][1], qa[s][2], qa[s][3], kb0b, kb1b);

                float p0 = ex2f(c0), p1 = ex2f(c1);
                float p2 = ex2f(c2), p3 = ex2f(c3);
                float p4 = ex2f(d0), p5 = ex2f(d1);
                float p6 = ex2f(d2), p7 = ex2f(d3);
                z[s][0] += (p0 + p1) + (p4 + p5);
                z[s][1] += (p2 + p3) + (p6 + p7);

                u32 pa0 = bf2(p0, p1), pa1 = bf2(p2, p3);
                u32 pa2 = bf2(p4, p5), pa3 = bf2(p6, p7);
                mma_bf16(cd[s][0][0], cd[s][0][1], cd[s][0][2], cd[s][0][3],
                         pa0, pa1, pa2, pa3, vb00, vb01);
                mma_bf16(cd[s][1][0], cd[s][1][1], cd[s][1][2], cd[s][1][3],
                         pa0, pa1, pa2, pa3, vb10, vb11);
            }
        }

        if (ch + 1 < S_ / KCHUNK) {
            int nxt = cur ^ 1;
            *(u32*)((char*)Ks[nxt] + key * 36 + d4 * 8)     = (u32)kvn;
            *(u32*)((char*)Ks[nxt] + key * 36 + d4 * 8 + 4) = (u32)(kvn >> 32);
            Vt[nxt][(d4 * 4 + 0) * 66 + key] = (u16)vvn;
            Vt[nxt][(d4 * 4 + 1) * 66 + key] = (u16)(vvn >> 16);
            Vt[nxt][(d4 * 4 + 2) * 66 + key] = (u16)(vvn >> 32);
            Vt[nxt][(d4 * 4 + 3) * 66 + key] = (u16)(vvn >> 48);
            if (tid < KCHUNK) bias[nxt][tid] = bbn;
            __syncthreads();
        }
    }

    int posA = h * 16 + tig * 4;
    int posB = posA + 2;
    #pragma unroll
    for (int s = 0; s < 2; ++s) {
        float z0 = z[s][0], z1 = z[s][1];
        z0 += __shfl_xor_sync(0xffffffffu, z0, 1);
        z0 += __shfl_xor_sync(0xffffffffu, z0, 2);
        z1 += __shfl_xor_sync(0xffffffffu, z1, 1);
        z1 += __shfl_xor_sync(0xffffffffu, z1, 2);

        size_t g0 = bS + qbase + w * 32 + s * 16 + gid;
        size_t g1 = g0 + 8;
        float rk0 = (nanf[g0] == 0.f) ? 1.f : 0.f;
        float rk1 = (nanf[g1] == 0.f) ? 1.f : 0.f;
        float rz0 = (rk0 != 0.f && z0 > 0.f) ? (1.f / z0) : 0.f;
        float rz1 = (rk1 != 0.f && z1 > 0.f) ? (1.f / z1) : 0.f;

        size_t row0 = g0 * 72;
        size_t row1 = g1 * 72;
        u32 hh, ll;
        split2(cd[s][0][0] * rz0, cd[s][0][1] * rz0, hh, ll);
        *(u32*)&cxh[row0 + posA] = hh; *(u32*)&cxl[row0 + posA] = ll;
        split2(cd[s][1][0] * rz0, cd[s][1][1] * rz0, hh, ll);
        *(u32*)&cxh[row0 + posB] = hh; *(u32*)&cxl[row0 + posB] = ll;
        split2(cd[s][0][2] * rz1, cd[s][0][3] * rz1, hh, ll);
        *(u32*)&cxh[row1 + posA] = hh; *(u32*)&cxl[row1 + posA] = ll;
        split2(cd[s][1][2] * rz1, cd[s][1][3] * rz1, hh, ll);
        *(u32*)&cxh[row1 + posB] = hh; *(u32*)&cxl[row1 + posB] = ll;
    }
}

// ------------------------- fused WO + LN1 + FFN + LN2 kernel -------------------
// Residual x comes from xh/xl frag reconstruction (no fp32 x tensor).
__global__ void __launch_bounds__(128) wo_ffn_kernel(
    const u16* __restrict__ cxh, const u16* __restrict__ cxl,
    const u16* __restrict__ wo_w, const u16* __restrict__ ws,
    const float* __restrict__ g1, const float* __restrict__ be1,
    const float* __restrict__ g2, const float* __restrict__ be2,
    const float* __restrict__ keep,
    u16* __restrict__ xh, u16* __restrict__ xl) {
    extern __shared__ u16 sw[];   // 4 * 64 * 72 u16 = 36864 B
    int tid = threadIdx.x, w = tid >> 5, lane = tid & 31;
    int gid = lane >> 2, tig = lane & 3;
    int m0 = blockIdx.x * 64;
    int r0 = m0 + w * 16 + gid;

    float C2[8][4];
    #pragma unroll
    for (int j = 0; j < 8; ++j)
        #pragma unroll
        for (int i = 0; i < 4; ++i) C2[j][i] = 0.f;
    {
        u32 Ah[4][4], Al[4][4];
        const u16* ph0 = cxh + (size_t)r0 * 72;
        const u16* ph8 = cxh + (size_t)(r0 + 8) * 72;
        const u16* pl0 = cxl + (size_t)r0 * 72;
        const u16* pl8 = cxl + (size_t)(r0 + 8) * 72;
        #pragma unroll
        for (int gk = 0; gk < 4; ++gk) {
            uint2 t0 = *(const uint2*)(ph0 + gk * 16 + tig * 4);
            uint2 t1 = *(const uint2*)(ph8 + gk * 16 + tig * 4);
            Ah[gk][0] = t0.x; Ah[gk][2] = t0.y;
            Ah[gk][1] = t1.x; Ah[gk][3] = t1.y;
            uint2 s0 = *(const uint2*)(pl0 + gk * 16 + tig * 4);
            uint2 s1 = *(const uint2*)(pl8 + gk * 16 + tig * 4);
            Al[gk][0] = s0.x; Al[gk][2] = s0.y;
            Al[gk][1] = s1.x; Al[gk][3] = s1.y;
        }
        const u16* Wh = wo_w;
        const u16* Wl = wo_w + 4608;
        #pragma unroll
        for (int j = 0; j < 8; ++j) {
            #pragma unroll
            for (int t = 0; t < 4; ++t) {
                uint2 bh = *(const uint2*)(Wh + (8 * j + gid) * 72 + t * 16 + tig * 4);
                uint2 bl = *(const uint2*)(Wl + (8 * j + gid) * 72 + t * 16 + tig * 4);
                mma_bf16(C2[j][0], C2[j][1], C2[j][2], C2[j][3], Ah[t][0], Ah[t][1], Ah[t][2], Ah[t][3], bh.x, bh.y);
                mma_bf16(C2[j][0], C2[j][1], C2[j][2], C2[j][3], Ah[t][0], Ah[t][1], Ah[t][2], Ah[t][3], bl.x, bl.y);
                mma_bf16(C2[j][0], C2[j][1], C2[j][2], C2[j][3], Al[t][0], Al[t][1], Al[t][2], Al[t][3], bh.x, bh.y);
            }
        }
    }

    float kp0 = keep[r0], kp1 = keep[r0 + 8];

    u32 A1h[4][4], A1l[4][4];
    {
        float v0[16], v1[16];
        float s0 = 0.f, q0 = 0.f, s1 = 0.f, q1 = 0.f;
        #pragma unroll
        for (int j = 0; j < 8; ++j) {
            int c = 8 * j + 2 * tig;
            int pos = pairpos(c);
            u32 xa_h = *(const u32*)&xh[(size_t)r0 * 72 + pos];
            u32 xa_l = *(const u32*)&xl[(size_t)r0 * 72 + pos];
            u32 xb_h = *(const u32*)&xh[(size_t)(r0 + 8) * 72 + pos];
            u32 xb_l = *(const u32*)&xl[(size_t)(r0 + 8) * 72 + pos];
            float a0v = C2[j][0] + (lopart(xa_h) + lopart(xa_l));
            float a1v = C2[j][1] + (hipart(xa_h) + hipart(xa_l));
            float b0v = C2[j][2] + (lopart(xb_h) + lopart(xb_l));
            float b1v = C2[j][3] + (hipart(xb_h) + hipart(xb_l));
            v0[2 * j] = a0v; v0[2 * j + 1] = a1v;
            v1[2 * j] = b0v; v1[2 * j + 1] = b1v;
            s0 += a0v + a1v; q0 += a0v * a0v + a1v * a1v;
            s1 += b0v + b1v; q1 += b0v * b0v + b1v * b1v;
        }
        s0 += __shfl_xor_sync(0xffffffffu, s0, 1); s0 += __shfl_xor_sync(0xffffffffu, s0, 2);
        q0 += __shfl_xor_sync(0xffffffffu, q0, 1); q0 += __shfl_xor_sync(0xffffffffu, q0, 2);
        s1 += __shfl_xor_sync(0xffffffffu, s1, 1); s1 += __shfl_xor_sync(0xffffffffu, s1, 2);
        q1 += __shfl_xor_sync(0xffffffffu, q1, 1); q1 += __shfl_xor_sync(0xffffffffu, q1, 2);
        float m0v = s0 * (1.f / 64.f), m1v = s1 * (1.f / 64.f);
        float i0 = rsqrtf(q0 * (1.f / 64.f) - m0v * m0v + 1e-6f);
        float i1 = rsqrtf(q1 * (1.f / 64.f) - m1v * m1v + 1e-6f);
        #pragma unroll
        for (int j = 0; j < 8; ++j) {
            int c = 8 * j + 2 * tig;
            float2 gg = *(const float2*)(g1 + c);
            float2 bb = *(const float2*)(be1 + c);
            float oax = ((v0[2 * j] - m0v) * i0 * gg.x + bb.x) * kp0;
            float oay = ((v0[2 * j + 1] - m0v) * i0 * gg.y + bb.y) * kp0;
            float obx = ((v1[2 * j] - m1v) * i1 * gg.x + bb.x) * kp1;
            float oby = ((v1[2 * j + 1] - m1v) * i1 * gg.y + bb.y) * kp1;
            int gk = j >> 1, half = (j & 1) << 1;
            split2(oax, oay, A1h[gk][half], A1l[gk][half]);
            split2(obx, oby, A1h[gk][half + 1], A1l[gk][half + 1]);
        }
    }

    #pragma unroll
    for (int j = 0; j < 8; ++j)
        #pragma unroll
        for (int i = 0; i < 4; ++i) C2[j][i] = 0.f;

    for (int nt = 0; nt < 4; ++nt) {
        __syncthreads();
        {
            const float4* src = (const float4*)(ws + (size_t)nt * 4 * 64 * 72);
            float4* dst = (float4*)sw;
            #pragma unroll
            for (int i = 0; i < 18; ++i) dst[tid + i * 128] = src[tid + i * 128];
        }
        __syncthreads();
        const u16* W1h = sw;
        const u16* W1l = sw + 64 * 72;
        const u16* W2h = sw + 2 * 64 * 72;
        const u16* W2l = sw + 3 * 64 * 72;

        u32 A2h[4][4], A2l[4][4];
        #pragma unroll
        for (int t = 0; t < 4; ++t) {
            float Ca[4] = {0.f, 0.f, 0.f, 0.f};
            float Cb[4] = {0.f, 0.f, 0.f, 0.f};
            #pragma unroll
            for (int gk = 0; gk < 4; ++gk) {
                uint2 bha = *(const uint2*)(W1h + (16 * t + gid) * 72 + gk * 16 + tig * 4);
                uint2 bla = *(const uint2*)(W1l + (16 * t + gid) * 72 + gk * 16 + tig * 4);
                mma_bf16(Ca[0], Ca[1], Ca[2], Ca[3], A1h[gk][0], A1h[gk][1], A1h[gk][2], A1h[gk][3], bha.x, bha.y);
                mma_bf16(Ca[0], Ca[1], Ca[2], Ca[3], A1h[gk][0], A1h[gk][1], A1h[gk][2], A1h[gk][3], bla.x, bla.y);
                mma_bf16(Ca[0], Ca[1], Ca[2], Ca[3], A1l[gk][0], A1l[gk][1], A1l[gk][2], A1l[gk][3], bha.x, bha.y);
                uint2 bhb = *(const uint2*)(W1h + (16 * t + 8 + gid) * 72 + gk * 16 + tig * 4);
                uint2 blb = *(const uint2*)(W1l + (16 * t + 8 + gid) * 72 + gk * 16 + tig * 4);
                mma_bf16(Cb[0], Cb[1], Cb[2], Cb[3], A1h[gk][0], A1h[gk][1], A1h[gk][2], A1h[gk][3], bhb.x, bhb.y);
                mma_bf16(Cb[0], Cb[1], Cb[2], Cb[3], A1h[gk][0], A1h[gk][1], A1h[gk][2], A1h[gk][3], blb.x, blb.y);
                mma_bf16(Cb[0], Cb[1], Cb[2], Cb[3], A1l[gk][0], A1l[gk][1], A1l[gk][2], A1l[gk][3], bhb.x, bhb.y);
            }
            #pragma unroll
            for (int i = 0; i < 4; ++i) { Ca[i] = fmaxf(Ca[i], 0.f); Cb[i] = fmaxf(Cb[i], 0.f); }
            split2(Ca[0], Ca[1], A2h[t][0], A2l[t][0]);
            split2(Ca[2], Ca[3], A2h[t][1], A2l[t][1]);
            split2(Cb[0], Cb[1], A2h[t][2], A2l[t][2]);
            split2(Cb[2], Cb[3], A2h[t][3], A2l[t][3]);
        }

        #pragma unroll
        for (int j = 0; j < 8; ++j) {
            #pragma unroll
            for (int t = 0; t < 4; ++t) {
                uint2 bh = *(const uint2*)(W2h + (8 * j + gid) * 72 + t * 16 + tig * 4);
                uint2 bl = *(const uint2*)(W2l + (8 * j + gid) * 72 + t * 16 + tig * 4);
                mma_bf16(C2[j][0], C2[j][1], C2[j][2], C2[j][3], A2h[t][0], A2h[t][1], A2h[t][2], A2h[t][3], bh.x, bh.y);
                mma_bf16(C2[j][0], C2[j][1], C2[j][2], C2[j][3], A2h[t][0], A2h[t][1], A2h[t][2], A2h[t][3], bl.x, bl.y);
                mma_bf16(C2[j][0], C2[j][1], C2[j][2], C2[j][3], A2l[t][0], A2l[t][1], A2l[t][2], A2l[t][3], bh.x, bh.y);
            }
        }
    }

    float v0[16], v1[16];
    float s0 = 0.f, q0 = 0.f, s1 = 0.f, q1 = 0.f;
    #pragma unroll
    for (int j = 0; j < 8; ++j) {
        int gk = j >> 1, half = (j & 1) << 1;
        float rax = lopart(A1h[gk][half])     + lopart(A1l[gk][half]);
        float ray = hipart(A1h[gk][half])     + hipart(A1l[gk][half]);
        float rbx = lopart(A1h[gk][half + 1]) + lopart(A1l[gk][half + 1]);
        float rby = hipart(A1h[gk][half + 1]) + hipart(A1l[gk][half + 1]);
        float a0v = C2[j][0] + rax, a1v = C2[j][1] + ray;
        float b0v = C2[j][2] + rbx, b1v = C2[j][3] + rby;
        v0[2 * j] = a0v; v0[2 * j + 1] = a1v;
        v1[2 * j] = b0v; v1[2 * j + 1] = b1v;
        s0 += a0v + a1v; q0 += a0v * a0v + a1v * a1v;
        s1 += b0v + b1v; q1 += b0v * b0v + b1v * b1v;
    }
    s0 += __shfl_xor_sync(0xffffffffu, s0, 1); s0 += __shfl_xor_sync(0xffffffffu, s0, 2);
    q0 += __shfl_xor_sync(0xffffffffu, q0, 1); q0 += __shfl_xor_sync(0xffffffffu, q0, 2);
    s1 += __shfl_xor_sync(0xffffffffu, s1, 1); s1 += __shfl_xor_sync(0xffffffffu, s1, 2);
    q1 += __shfl_xor_sync(0xffffffffu, q1, 1); q1 += __shfl_xor_sync(0xffffffffu, q1, 2);
    float m0v = s0 * (1.f / 64.f), m1v = s1 * (1.f / 64.f);
    float i0 = rsqrtf(q0 * (1.f / 64.f) - m0v * m0v + 1e-6f);
    float i1 = rsqrtf(q1 * (1.f / 64.f) - m1v * m1v + 1e-6f);
    #pragma unroll
    for (int j = 0; j < 8; ++j) {
        int c = 8 * j + 2 * tig;
        float2 gg = *(const float2*)(g2 + c);
        float2 bb = *(const float2*)(be2 + c);
        float oax = ((v0[2 * j] - m0v) * i0 * gg.x + bb.x) * kp0;
        float oay = ((v0[2 * j + 1] - m0v) * i0 * gg.y + bb.y) * kp0;
        float obx = ((v1[2 * j] - m1v) * i1 * gg.x + bb.x) * kp1;
        float oby = ((v1[2 * j + 1] - m1v) * i1 * gg.y + bb.y) * kp1;
        int pos = pairpos(c);
        u32 hh, ll;
        split2(oax, oay, hh, ll);
        *(u32*)&xh[(size_t)r0 * 72 + pos] = hh; *(u32*)&xl[(size_t)r0 * 72 + pos] = ll;
        split2(obx, oby, hh, ll);
        *(u32*)&xh[(size_t)(r0 + 8) * 72 + pos] = hh; *(u32*)&xl[(size_t)(r0 + 8) * 72 + pos] = ll;
    }
}

// ------------------------- tensor-core classifier ------------------------------
__global__ void __launch_bounds__(128) cls_mma_kernel(
    const u16* __restrict__ xh, const u16* __restrict__ xl,
    const u16* __restrict__ wcls,   // [w1h|w1l|w2h|w2l], each 4608 u16
    const float* __restrict__ b1, const float* __restrict__ b2,
    const float* __restrict__ w3, const float* __restrict__ b3,
    float* __restrict__ part) {
    __shared__ __align__(16) u16 sw[4 * 4608];   // 36864 B
    __shared__ float red[128];
    int tid = threadIdx.x, w = tid >> 5, lane = tid & 31;
    int gid = lane >> 2, tig = lane & 3;
    int m0 = blockIdx.x * 64;
    int r0 = m0 + w * 16 + gid;

    {
        const float4* src = (const float4*)wcls;
        float4* dst = (float4*)sw;
        #pragma unroll
        for (int i = 0; i < 18; ++i) dst[tid + i * 128] = src[tid + i * 128];
    }

    u32 Ah[4][4], Al[4][4];
    {
        const u16* ph0 = xh + (size_t)r0 * 72;
        const u16* ph8 = xh + (size_t)(r0 + 8) * 72;
        const u16* pl0 = xl + (size_t)r0 * 72;
        const u16* pl8 = xl + (size_t)(r0 + 8) * 72;
        #pragma unroll
        for (int gk = 0; gk < 4; ++gk) {
            uint2 t0 = *(const uint2*)(ph0 + gk * 16 + tig * 4);
            uint2 t1 = *(const uint2*)(ph8 + gk * 16 + tig * 4);
            Ah[gk][0] = t0.x; Ah[gk][2] = t0.y;
            Ah[gk][1] = t1.x; Ah[gk][3] = t1.y;
            uint2 s0 = *(const uint2*)(pl0 + gk * 16 + tig * 4);
            uint2 s1 = *(const uint2*)(pl8 + gk * 16 + tig * 4);
            Al[gk][0] = s0.x; Al[gk][2] = s0.y;
            Al[gk][1] = s1.x; Al[gk][3] = s1.y;
        }
    }
    __syncthreads();
    const u16* W1h = sw;
    const u16* W1l = sw + 4608;
    const u16* W2h = sw + 2 * 4608;
    const u16* W2l = sw + 3 * 4608;

    u32 A2h[4][4], A2l[4][4];
    #pragma unroll
    for (int t = 0; t < 4; ++t) {
        float Ca[4] = {0.f, 0.f, 0.f, 0.f};
        float Cb[4] = {0.f, 0.f, 0.f, 0.f};
        #pragma unroll
        for (int gk = 0; gk < 4; ++gk) {
            uint2 bha = *(const uint2*)(W1h + (16 * t + gid) * 72 + gk * 16 + tig * 4);
            uint2 bla = *(const uint2*)(W1l + (16 * t + gid) * 72 + gk * 16 + tig * 4);
            mma_bf16(Ca[0], Ca[1], Ca[2], Ca[3], Ah[gk][0], Ah[gk][1], Ah[gk][2], Ah[gk][3], bha.x, bha.y);
            mma_bf16(Ca[0], Ca[1], Ca[2], Ca[3], Ah[gk][0], Ah[gk][1], Ah[gk][2], Ah[gk][3], bla.x, bla.y);
            mma_bf16(Ca[0], Ca[1], Ca[2], Ca[3], Al[gk][0], Al[gk][1], Al[gk][2], Al[gk][3], bha.x, bha.y);
            uint2 bhb = *(const uint2*)(W1h + (16 * t + 8 + gid) * 72 + gk * 16 + tig * 4);
            uint2 blb = *(const uint2*)(W1l + (16 * t + 8 + gid) * 72 + gk * 16 + tig * 4);
            mma_bf16(Cb[0], Cb[1], Cb[2], Cb[3], Ah[gk][0], Ah[gk][1], Ah[gk][2], Ah[gk][3], bhb.x, bhb.y);
            mma_bf16(Cb[0], Cb[1], Cb[2], Cb[3], Ah[gk][0], Ah[gk][1], Ah[gk][2], Ah[gk][3], blb.x, blb.y);
            mma_bf16(Cb[0], Cb[1], Cb[2], Cb[3], Al[gk][0], Al[gk][1], Al[gk][2], Al[gk][3], bhb.x, bhb.y);
        }
        float2 b1a = *(const float2*)(b1 + 16 * t + 2 * tig);
        float2 b1b = *(const float2*)(b1 + 16 * t + 8 + 2 * tig);
        Ca[0] = fmaxf(Ca[0] + b1a.x, 0.f); Ca[1] = fmaxf(Ca[1] + b1a.y, 0.f);
        Ca[2] = fmaxf(Ca[2] + b1a.x, 0.f); Ca[3] = fmaxf(Ca[3] + b1a.y, 0.f);
        Cb[0] = fmaxf(Cb[0] + b1b.x, 0.f); Cb[1] = fmaxf(Cb[1] + b1b.y, 0.f);
        Cb[2] = fmaxf(Cb[2] + b1b.x, 0.f); Cb[3] = fmaxf(Cb[3] + b1b.y, 0.f);
        split2(Ca[0], Ca[1], A2h[t][0], A2l[t][0]);
        split2(Ca[2], Ca[3], A2h[t][1], A2l[t][1]);
        split2(Cb[0], Cb[1], A2h[t][2], A2l[t][2]);
        split2(Cb[2], Cb[3], A2h[t][3], A2l[t][3]);
    }

    float partial = 0.f;
    #pragma unroll
    for (int j = 0; j < 8; ++j) {
        float C2[4] = {0.f, 0.f, 0.f, 0.f};
        #pragma unroll
        for (int t = 0; t < 4; ++t) {
            uint2 bh = *(const uint2*)(W2h + (8 * j + gid) * 72 + t * 16 + tig * 4);
            uint2 bl = *(const uint2*)(W2l + (8 * j + gid) * 72 + t * 16 + tig * 4);
            mma_bf16(C2[0], C2[1], C2[2], C2[3], A2h[t][0], A2h[t][1], A2h[t][2], A2h[t][3], bh.x, bh.y);
            mma_bf16(C2[0], C2[1], C2[2], C2[3], A2h[t][0], A2h[t][1], A2h[t][2], A2h[t][3], bl.x, bl.y);
            mma_bf16(C2[0], C2[1], C2[2], C2[3], A2l[t][0], A2l[t][1], A2l[t][2], A2l[t][3], bh.x, bh.y);
        }
        int c = 8 * j + 2 * tig;
        float2 b2v = *(const float2*)(b2 + c);
        float2 w3v = *(const float2*)(w3 + c);
        partial += fmaxf(C2[0] + b2v.x, 0.f) * w3v.x + fmaxf(C2[1] + b2v.y, 0.f) * w3v.y;
        partial += fmaxf(C2[2] + b2v.x, 0.f) * w3v.x + fmaxf(C2[3] + b2v.y, 0.f) * w3v.y;
    }
    red[tid] = partial;
    __syncthreads();
    for (int st = 64; st > 0; st >>= 1) {
        if (tid < st) red[tid] += red[tid + st];
        __syncthreads();
    }
    if (tid == 0) part[blockIdx.x] = red[0] + 64.f * b3[0];
}

// ------------------------- deterministic final reduction ----------------------
__global__ void reduce_y(const float* __restrict__ part,
                         const float* __restrict__ ob, float* __restrict__ y) {
    int b = threadIdx.x;   // 16
    float s = ob[0];
    #pragma unroll
    for (int i = 0; i < 16; ++i) s += part[b * 16 + i];
    y[b] = s;
}

// ------------------------- launcher ------------------------------------------
extern "C" void kernel_launch(void* const* d_in, const int* in_sizes, int n_in,
                              void* d_out, int out_size) {
    const float* input  = (const float*)d_in[0];
    const float* emb    = (const float*)d_in[1];
    const float* wq     = (const float*)d_in[2];
    const float* wq_b   = (const float*)d_in[3];
    const float* wk     = (const float*)d_in[4];
    const float* wk_b   = (const float*)d_in[5];
    const float* wv     = (const float*)d_in[6];
    const float* wv_b   = (const float*)d_in[7];
    const float* wo     = (const float*)d_in[8];
    const float* ffn_w1 = (const float*)d_in[9];
    const float* ffn_w2 = (const float*)d_in[10];
    const float* ln1_g  = (const float*)d_in[11];
    const float* ln1_b  = (const float*)d_in[12];
    const float* ln2_g  = (const float*)d_in[13];
    const float* ln2_b  = (const float*)d_in[14];
    const float* c_w1   = (const float*)d_in[15];
    const float* c_b1   = (const float*)d_in[16];
    const float* c_w2   = (const float*)d_in[17];
    const float* c_b2   = (const float*)d_in[18];
    const float* c_w3   = (const float*)d_in[19];
    const float* c_b3   = (const float*)d_in[20];
    const float* ob     = (const float*)d_in[21];
    float* y = (float*)d_out;

    float *keep, *nanf, *gbias, *part;
    u16 *ws, *wqkvo, *wcls, *xh, *xl, *cxh, *cxl, *qb, *kbp, *vbp;
    cudaGetSymbolAddress((void**)&keep, g_keep);
    cudaGetSymbolAddress((void**)&nanf, g_nanf);
    cudaGetSymbolAddress((void**)&gbias, g_bias);
    cudaGetSymbolAddress((void**)&part, g_part);
    cudaGetSymbolAddress((void**)&ws,   g_ws);
    cudaGetSymbolAddress((void**)&wqkvo, g_wqkvo);
    cudaGetSymbolAddress((void**)&wcls, g_wcls);
    cudaGetSymbolAddress((void**)&xh,   g_xh);
    cudaGetSymbolAddress((void**)&xl,   g_xl);
    cudaGetSymbolAddress((void**)&cxh,  g_cxh);
    cudaGetSymbolAddress((void**)&cxl,  g_cxl);
    cudaGetSymbolAddress((void**)&qb,   g_qb);
    cudaGetSymbolAddress((void**)&kbp,  g_kb);
    cudaGetSymbolAddress((void**)&vbp,  g_vb);

    const int FFN_SMEM = 4 * 64 * 72 * 2;         // 36864 B
    cudaFuncSetAttribute(wo_ffn_kernel, cudaFuncAttributeMaxDynamicSharedMemorySize, FFN_SMEM);

    prep_kernel<<<B_, S_>>>(input, keep, nanf, gbias);
    build_x_kernel<<<(BS * 32) / 256, 256>>>(input, emb, keep, xh, xl);
    wprep_all_kernel<<<416, 256>>>(wq, wk, wv, wo, ffn_w1, ffn_w2, c_w1, c_w2,
                                   wqkvo, ws, wcls);

    for (int l = 0; l < L_; ++l) {
        const u16* wqkv_l = wqkvo + (size_t)l * 8 * 4608;       // q,k,v regions
        const u16* wo_l   = wqkvo + ((size_t)l * 8 + 6) * 4608; // o region

        qkv_mma_kernel<<<dim3(BS / 64, 3), 128>>>(
            xh, wqkv_l, wq_b + l * D_, wk_b + l * D_, wv_b + l * D_, qb, kbp, vbp);
        attn_mma_kernel<<<dim3(S_ / 256, B_ * H_), 256>>>(qb, kbp, vbp, gbias, nanf, cxh, cxl);
        wo_ffn_kernel<<<BS / 64, 128, FFN_SMEM>>>(
            cxh, cxl, wo_l, ws + (size_t)l * 4 * 4 * 64 * 72,
            ln1_g + l * D_, ln1_b + l * D_, ln2_g + l * D_, ln2_b + l * D_,
            keep, xh, xl);
    }

    cls_mma_kernel<<<BS / 64, 128>>>(xh, xl, wcls, c_b1, c_b2, c_w3, c_b3, part);
    reduce_y<<<1, 16>>>(part, ob, y);
}